// round 1
// baseline (speedup 1.0000x reference)
#include <cuda_runtime.h>
#include <math.h>

#define BB 64
#define SS 512
#define DD 1024
#define HH 1024
#define GG 4096  // 4*H

// ---------------- scratch (device globals; no allocation allowed) ----------
__device__ float g_xg[(size_t)BB * SS * GG];   // 512 MB: precomputed x @ Wi^T + bi
__device__ float g_hbuf[2][BB * HH];           // ping-pong hidden state
__device__ float g_cbuf[BB * HH];              // cell state (in-place, block-owned)

// ---------------- init h,c broadcast ---------------------------------------
__global__ void init_state(const float* __restrict__ h0, const float* __restrict__ c0) {
    int i = blockIdx.x * blockDim.x + threadIdx.x;
    if (i < BB * HH) {
        int j = i % HH;
        g_hbuf[0][i] = h0[j];
        g_cbuf[i]    = c0[j];
    }
}

// ---------------- big input GEMM: xg[M=BS][N=4H] = x[M][K] * Wi[N][K]^T + bi
#define BM 128
#define BN 128
#define BK 16

__global__ __launch_bounds__(256) void gemm_xg(const float* __restrict__ x,
                                               const float* __restrict__ Wi,
                                               const float* __restrict__ bi) {
    __shared__ float As[BK][BM];
    __shared__ float Bs[BK][BN];

    const int m0 = blockIdx.y * BM;
    const int n0 = blockIdx.x * BN;
    const int tid = threadIdx.x;
    const int tx = tid % 16;          // 16 col-groups * 8 = 128
    const int ty = tid / 16;          // 16 row-groups * 8 = 128

    // load mapping: each thread loads 2x float4 per operand tile
    const int lr = tid / 4;           // 0..63
    const int lk = (tid % 4) * 4;     // 0,4,8,12

    float acc[8][8];
#pragma unroll
    for (int i = 0; i < 8; i++)
#pragma unroll
        for (int j = 0; j < 8; j++) acc[i][j] = 0.f;

    for (int k0 = 0; k0 < DD; k0 += BK) {
        float4 a0 = *(const float4*)&x[(size_t)(m0 + lr) * DD + k0 + lk];
        float4 a1 = *(const float4*)&x[(size_t)(m0 + lr + 64) * DD + k0 + lk];
        float4 b0 = *(const float4*)&Wi[(size_t)(n0 + lr) * DD + k0 + lk];
        float4 b1 = *(const float4*)&Wi[(size_t)(n0 + lr + 64) * DD + k0 + lk];
        As[lk + 0][lr] = a0.x; As[lk + 1][lr] = a0.y; As[lk + 2][lr] = a0.z; As[lk + 3][lr] = a0.w;
        As[lk + 0][lr + 64] = a1.x; As[lk + 1][lr + 64] = a1.y; As[lk + 2][lr + 64] = a1.z; As[lk + 3][lr + 64] = a1.w;
        Bs[lk + 0][lr] = b0.x; Bs[lk + 1][lr] = b0.y; Bs[lk + 2][lr] = b0.z; Bs[lk + 3][lr] = b0.w;
        Bs[lk + 0][lr + 64] = b1.x; Bs[lk + 1][lr + 64] = b1.y; Bs[lk + 2][lr + 64] = b1.z; Bs[lk + 3][lr + 64] = b1.w;
        __syncthreads();

#pragma unroll
        for (int kk = 0; kk < BK; kk++) {
            float4 av0 = *(const float4*)&As[kk][ty * 8];
            float4 av1 = *(const float4*)&As[kk][ty * 8 + 4];
            float4 bv0 = *(const float4*)&Bs[kk][tx * 8];
            float4 bv1 = *(const float4*)&Bs[kk][tx * 8 + 4];
            float a[8] = {av0.x, av0.y, av0.z, av0.w, av1.x, av1.y, av1.z, av1.w};
            float b[8] = {bv0.x, bv0.y, bv0.z, bv0.w, bv1.x, bv1.y, bv1.z, bv1.w};
#pragma unroll
            for (int i = 0; i < 8; i++)
#pragma unroll
                for (int j = 0; j < 8; j++) acc[i][j] += a[i] * b[j];
        }
        __syncthreads();
    }

    // epilogue: add bias, store
#pragma unroll
    for (int i = 0; i < 8; i++) {
        int m = m0 + ty * 8 + i;
        float* dst = &g_xg[(size_t)m * GG + n0 + tx * 8];
#pragma unroll
        for (int j = 0; j < 8; j++) dst[j] = acc[i][j] + bi[n0 + tx * 8 + j];
    }
}

// ---------------- recurrent step -------------------------------------------
// block owns SB_J hidden units -> 32 gate columns (4 segments x 8), all 64 batches.
#define SB_J 8
#define SB_N 32
#define SB_K 16

__global__ __launch_bounds__(256) void lstm_step(const float* __restrict__ Wh,
                                                 const float* __restrict__ bh,
                                                 float* __restrict__ out,
                                                 int t, int ping) {
    __shared__ float As[SB_K][BB];       // h tile   [k][b]
    __shared__ float Bs[SB_K][SB_N];     // Wh tile  [k][n]
    __shared__ float Gs[BB][SB_N];       // gates

    const float* __restrict__ h_in = g_hbuf[ping];
    float* __restrict__ h_out = g_hbuf[ping ^ 1];

    const int j0 = blockIdx.x * SB_J;
    const int tid = threadIdx.x;
    const int tx = tid % 16;   // 16 * 2 cols = 32
    const int ty = tid / 16;   // 16 * 4 rows = 64

    // A-load: 64 x 16 floats, 1 float4/thread
    const int ab = tid / 4;
    const int ak = (tid % 4) * 4;
    // B-load: 32 x 16 floats, 1 float2/thread
    const int bn = tid / 8;
    const int bk = (tid % 8) * 2;
    const int bseg = bn / SB_J, bjj = bn % SB_J;
    const float* whrow = Wh + (size_t)(bseg * HH + j0 + bjj) * HH;

    float acc[4][2] = {{0.f, 0.f}, {0.f, 0.f}, {0.f, 0.f}, {0.f, 0.f}};

    for (int k0 = 0; k0 < HH; k0 += SB_K) {
        float4 av = *(const float4*)&h_in[(size_t)ab * HH + k0 + ak];
        As[ak + 0][ab] = av.x; As[ak + 1][ab] = av.y;
        As[ak + 2][ab] = av.z; As[ak + 3][ab] = av.w;
        float2 bv = *(const float2*)&whrow[k0 + bk];
        Bs[bk + 0][bn] = bv.x; Bs[bk + 1][bn] = bv.y;
        __syncthreads();

#pragma unroll
        for (int kk = 0; kk < SB_K; kk++) {
            float4 a = *(const float4*)&As[kk][ty * 4];
            float2 b = *(const float2*)&Bs[kk][tx * 2];
            acc[0][0] += a.x * b.x; acc[0][1] += a.x * b.y;
            acc[1][0] += a.y * b.x; acc[1][1] += a.y * b.y;
            acc[2][0] += a.z * b.x; acc[2][1] += a.z * b.y;
            acc[3][0] += a.w * b.x; acc[3][1] += a.w * b.y;
        }
        __syncthreads();
    }

    // gates = acc + xg[b][t][gcol] + bh[gcol]
#pragma unroll
    for (int i = 0; i < 4; i++) {
#pragma unroll
        for (int j = 0; j < 2; j++) {
            int m = ty * 4 + i;            // batch
            int n = tx * 2 + j;            // local gate col
            int seg = n / SB_J, jj = n % SB_J;
            int gcol = seg * HH + j0 + jj;
            float v = acc[i][j] + bh[gcol] + g_xg[((size_t)m * SS + t) * GG + gcol];
            Gs[m][n] = v;
        }
    }
    __syncthreads();

    // nonlinearity + state update: 64*8 = 512 cells
    for (int cell = tid; cell < BB * SB_J; cell += 256) {
        int b = cell / SB_J, jj = cell % SB_J;
        float gi = Gs[b][0 * SB_J + jj];
        float gf = Gs[b][1 * SB_J + jj];
        float gg = Gs[b][2 * SB_J + jj];
        float go = Gs[b][3 * SB_J + jj];
        float iv = 1.f / (1.f + expf(-gi));
        float fv = 1.f / (1.f + expf(-gf));
        float gv = tanhf(gg);
        float ov = 1.f / (1.f + expf(-go));
        int j = j0 + jj;
        float c = fv * g_cbuf[(size_t)b * HH + j] + iv * gv;
        g_cbuf[(size_t)b * HH + j] = c;
        float h = ov * tanhf(c);
        h_out[(size_t)b * HH + j] = h;
        out[((size_t)b * SS + t) * HH + j] = h;
    }
}

// ---------------- tail: final (h, c) if out_size includes them --------------
__global__ void write_tail(float* __restrict__ out, long long hsz,
                           int want_h, int want_c, int final_buf) {
    int i = blockIdx.x * blockDim.x + threadIdx.x;
    if (i < BB * HH) {
        if (want_h) out[hsz + i] = g_hbuf[final_buf][i];
        if (want_c) out[hsz + (long long)BB * HH + i] = g_cbuf[i];
    }
}

// ---------------- launch -----------------------------------------------------
extern "C" void kernel_launch(void* const* d_in, const int* in_sizes, int n_in,
                              void* d_out, int out_size) {
    const float* x  = (const float*)d_in[0];
    const float* h0 = (const float*)d_in[1];
    const float* c0 = (const float*)d_in[2];
    const float* Wi = (const float*)d_in[3];
    const float* bi = (const float*)d_in[4];
    const float* Wh = (const float*)d_in[5];
    const float* bh = (const float*)d_in[6];
    float* out = (float*)d_out;

    init_state<<<(BB * HH + 255) / 256, 256>>>(h0, c0);

    dim3 g1(GG / BN, (BB * SS) / BM);
    gemm_xg<<<g1, 256>>>(x, Wi, bi);

    for (int t = 0; t < SS; t++) {
        lstm_step<<<HH / SB_J, 256>>>(Wh, bh, out, t, t & 1);
    }

    long long hsz = (long long)BB * SS * HH;
    int want_h = ((long long)out_size >= hsz + (long long)BB * HH) ? 1 : 0;
    int want_c = ((long long)out_size >= hsz + 2LL * BB * HH) ? 1 : 0;
    if (want_h) {
        // after 512 steps (even), final h lives in buffer 0
        write_tail<<<(BB * HH + 255) / 256, 256>>>(out, hsz, want_h, want_c, 0);
    }
}

// round 2
// speedup vs baseline: 1.0771x; 1.0771x over previous
#include <cuda_runtime.h>
#include <math.h>

#define BB 64
#define SS 512
#define DD 1024
#define HH 1024
#define GG 4096
#define KC 16

typedef unsigned long long ull;

__device__ __forceinline__ ull ffma2(ull a, ull b, ull c) {
    ull d;
    asm("fma.rn.f32x2 %0, %1, %2, %3;" : "=l"(d) : "l"(a), "l"(b), "l"(c));
    return d;
}
__device__ __forceinline__ void cp_async16(unsigned s, const void* g) {
    asm volatile("cp.async.ca.shared.global [%0], [%1], 16;" :: "r"(s), "l"(g));
}
__device__ __forceinline__ void cp_commit() { asm volatile("cp.async.commit_group;"); }
template<int N> __device__ __forceinline__ void cp_wait() {
    asm volatile("cp.async.wait_group %0;" :: "n"(N));
}

// permuted gate-col index p in [0,4096): p = j*4 + seg  ->  source row g = seg*1024 + j
__host__ __device__ __forceinline__ int gmap(int p) { return (p & 3) * 1024 + (p >> 2); }

// ---------------- device scratch --------------------------------------------
__device__ float  g_xg[(size_t)BB * SS * GG];   // xg + bias, permuted cols
__device__ float2 g_Wh2T[(size_t)HH * GG];      // [k][p] duplicated pairs (32MB)
__device__ float  g_hT[2][HH * BB];             // transposed h: [j][b]
__device__ float  g_cbuf[BB * HH];
__device__ float  g_bias[GG];                   // permuted bi+bh

// ---------------- init -------------------------------------------------------
__global__ void init_state(const float* __restrict__ h0, const float* __restrict__ c0,
                           const float* __restrict__ bi, const float* __restrict__ bh) {
    int i = blockIdx.x * blockDim.x + threadIdx.x;
    if (i < BB * HH) {
        int b = i / HH, j = i % HH;
        g_cbuf[i] = c0[j];
        g_hT[0][j * BB + b] = h0[j];
    }
    if (i < GG) {
        int g = gmap(i);
        g_bias[i] = bi[g] + bh[g];
    }
}

__global__ void prep_wh(const float* __restrict__ Wh) {
    int idx = blockIdx.x * blockDim.x + threadIdx.x;
    if (idx < HH * GG) {
        int k = idx & (HH - 1);
        int p = idx >> 10;
        float v = Wh[(size_t)gmap(p) * HH + k];
        g_Wh2T[(size_t)k * GG + p] = make_float2(v, v);
    }
}

// ---------------- input GEMM (f32x2 inner loop, permuted cols) ---------------
#define BM 128
#define BN 128
#define BK 16

__global__ __launch_bounds__(256) void gemm_xg(const float* __restrict__ x,
                                               const float* __restrict__ Wi) {
    __shared__ float2 As2[BK][BM];   // duplicated pairs
    __shared__ float  Bs[BK][BN];

    const int m0 = blockIdx.y * BM;
    const int n0 = blockIdx.x * BN;  // permuted col space
    const int tid = threadIdx.x;
    const int tx = tid % 16;
    const int ty = tid / 16;
    const int lr = tid / 4;
    const int lk = (tid % 4) * 4;

    const int g1 = gmap(n0 + lr);
    const int g2 = gmap(n0 + lr + 64);

    ull acc[8][4];
#pragma unroll
    for (int i = 0; i < 8; i++)
#pragma unroll
        for (int j = 0; j < 4; j++) acc[i][j] = 0ULL;

    for (int k0 = 0; k0 < DD; k0 += BK) {
        float4 a0 = *(const float4*)&x[(size_t)(m0 + lr) * DD + k0 + lk];
        float4 a1 = *(const float4*)&x[(size_t)(m0 + lr + 64) * DD + k0 + lk];
        float4 b0 = *(const float4*)&Wi[(size_t)g1 * DD + k0 + lk];
        float4 b1 = *(const float4*)&Wi[(size_t)g2 * DD + k0 + lk];
        As2[lk + 0][lr] = make_float2(a0.x, a0.x);
        As2[lk + 1][lr] = make_float2(a0.y, a0.y);
        As2[lk + 2][lr] = make_float2(a0.z, a0.z);
        As2[lk + 3][lr] = make_float2(a0.w, a0.w);
        As2[lk + 0][lr + 64] = make_float2(a1.x, a1.x);
        As2[lk + 1][lr + 64] = make_float2(a1.y, a1.y);
        As2[lk + 2][lr + 64] = make_float2(a1.z, a1.z);
        As2[lk + 3][lr + 64] = make_float2(a1.w, a1.w);
        Bs[lk + 0][lr] = b0.x; Bs[lk + 1][lr] = b0.y;
        Bs[lk + 2][lr] = b0.z; Bs[lk + 3][lr] = b0.w;
        Bs[lk + 0][lr + 64] = b1.x; Bs[lk + 1][lr + 64] = b1.y;
        Bs[lk + 2][lr + 64] = b1.z; Bs[lk + 3][lr + 64] = b1.w;
        __syncthreads();

#pragma unroll
        for (int kk = 0; kk < BK; kk++) {
            const ull* ap = (const ull*)&As2[kk][ty * 8];
            ulonglong2 A0 = *(const ulonglong2*)(ap);
            ulonglong2 A1 = *(const ulonglong2*)(ap + 2);
            ulonglong2 A2 = *(const ulonglong2*)(ap + 4);
            ulonglong2 A3 = *(const ulonglong2*)(ap + 6);
            const ull* bp = (const ull*)&Bs[kk][tx * 8];
            ulonglong2 B0 = *(const ulonglong2*)(bp);
            ulonglong2 B1 = *(const ulonglong2*)(bp + 2);
            ull a[8] = {A0.x, A0.y, A1.x, A1.y, A2.x, A2.y, A3.x, A3.y};
            ull b[4] = {B0.x, B0.y, B1.x, B1.y};
#pragma unroll
            for (int i = 0; i < 8; i++)
#pragma unroll
                for (int j = 0; j < 4; j++) acc[i][j] = ffma2(a[i], b[j], acc[i][j]);
        }
        __syncthreads();
    }

    const int bc = n0 + tx * 8;
    float4 bv0 = *(const float4*)&g_bias[bc];
    float4 bv1 = *(const float4*)&g_bias[bc + 4];
    float bias[8] = {bv0.x, bv0.y, bv0.z, bv0.w, bv1.x, bv1.y, bv1.z, bv1.w};
#pragma unroll
    for (int i = 0; i < 8; i++) {
        int m = m0 + ty * 8 + i;
        float* dst = &g_xg[(size_t)m * GG + bc];
#pragma unroll
        for (int j = 0; j < 4; j++) {
            float2 v = *(float2*)&acc[i][j];
            dst[2 * j] = v.x + bias[2 * j];
            dst[2 * j + 1] = v.y + bias[2 * j + 1];
        }
    }
}

// ---------------- recurrent step ---------------------------------------------
// 128 blocks x 256 threads. Block owns 32 permuted gate cols (8 hidden units).
// Warp w owns K range [w*128, w*128+128), double-buffered cp.async staging.
extern __shared__ char smx[];

__device__ __forceinline__ void step_prefetch(char* warpbase, int buf, int w, int cc,
                                              int lane, const float* hT, int c0) {
    const int k0 = w * 128 + cc * KC;
    unsigned hdst = (unsigned)__cvta_generic_to_shared(warpbase + buf * 8192);
    const char* hsrc = (const char*)(hT + (size_t)k0 * BB) + lane * 128;
    unsigned d0 = hdst + lane * 128;
#pragma unroll
    for (int i = 0; i < 8; i++) cp_async16(d0 + i * 16, hsrc + i * 16);
    const int r = lane >> 1, half = lane & 1;
    unsigned wdst = hdst + 4096 + r * 256 + half * 128;
    const char* wsrc = (const char*)(g_Wh2T + ((size_t)(k0 + r) * GG + c0)) + half * 128;
#pragma unroll
    for (int i = 0; i < 8; i++) cp_async16(wdst + i * 16, wsrc + i * 16);
    cp_commit();
}

__global__ __launch_bounds__(256) void lstm_step(float* __restrict__ out, int t, int ping) {
    const int tid = threadIdx.x;
    const int w = tid >> 5, lane = tid & 31;
    const int ty = lane >> 2, tx = lane & 3;
    const int bx = blockIdx.x;
    const int c0 = bx * 32;
    char* warpbase = smx + w * 16384;
    ull* pp = (ull*)(smx + 131072);            // partials [8][32][32] f32x2
    float* gatesS = (float*)(smx + 196608);    // [64][32]
    const float* hT = g_hT[ping];
    float* hTo = g_hT[ping ^ 1];

    ull acc[4][8];
#pragma unroll
    for (int i = 0; i < 4; i++)
#pragma unroll
        for (int j = 0; j < 8; j++) acc[i][j] = 0ULL;

    step_prefetch(warpbase, 0, w, 0, lane, hT, c0);

    for (int cc = 0; cc < 8; cc++) {
        if (cc < 7) {
            step_prefetch(warpbase, (cc + 1) & 1, w, cc + 1, lane, hT, c0);
            cp_wait<1>();
        } else {
            cp_wait<0>();
        }
        __syncwarp();
        const ull* hp = (const ull*)(warpbase + (cc & 1) * 8192);
        const ull* wp = hp + 512;
#pragma unroll
        for (int kk = 0; kk < KC; kk++) {
            ulonglong2 A0 = *(const ulonglong2*)(hp + kk * 32 + ty * 4);
            ulonglong2 A1 = *(const ulonglong2*)(hp + kk * 32 + ty * 4 + 2);
            ulonglong2 W0 = *(const ulonglong2*)(wp + kk * 32 + tx * 8);
            ulonglong2 W1 = *(const ulonglong2*)(wp + kk * 32 + tx * 8 + 2);
            ulonglong2 W2 = *(const ulonglong2*)(wp + kk * 32 + tx * 8 + 4);
            ulonglong2 W3 = *(const ulonglong2*)(wp + kk * 32 + tx * 8 + 6);
            ull a[4] = {A0.x, A0.y, A1.x, A1.y};
            ull wv[8] = {W0.x, W0.y, W1.x, W1.y, W2.x, W2.y, W3.x, W3.y};
#pragma unroll
            for (int bp2 = 0; bp2 < 4; bp2++)
#pragma unroll
                for (int c = 0; c < 8; c++)
                    acc[bp2][c] = ffma2(a[bp2], wv[c], acc[bp2][c]);
        }
        __syncwarp();
    }

    // partials to SMEM
    const int pbase = w * 1024 + (ty * 4) * 32 + tx * 8;
#pragma unroll
    for (int bp2 = 0; bp2 < 4; bp2++)
#pragma unroll
        for (int c = 0; c < 8; c++)
            pp[pbase + bp2 * 32 + c] = acc[bp2][c];
    __syncthreads();

    // reduce 8 partials -> gates
#pragma unroll
    for (int q = 0; q < 4; q++) {
        int idx = tid * 4 + q;
        int bpg = idx >> 5, col = idx & 31;
        float sx = 0.f, sy = 0.f;
#pragma unroll
        for (int w8 = 0; w8 < 8; w8++) {
            ull v = pp[w8 * 1024 + bpg * 32 + col];
            float2 f = *(float2*)&v;
            sx += f.x; sy += f.y;
        }
        gatesS[(bpg * 2) * 32 + col] = sx;
        gatesS[(bpg * 2 + 1) * 32 + col] = sy;
    }
    __syncthreads();

    // epilogue: 2 cells per thread
    {
        const int b = tid >> 2, cg = tid & 3;
        float4 gq0 = *(const float4*)&gatesS[b * 32 + cg * 8];
        float4 gq1 = *(const float4*)&gatesS[b * 32 + cg * 8 + 4];
        const float* xrow = g_xg + ((size_t)b * SS + t) * GG + c0 + cg * 8;
        float4 x0 = *(const float4*)xrow;
        float4 x1 = *(const float4*)(xrow + 4);

        float gi0 = gq0.x + x0.x, gf0 = gq0.y + x0.y, gg0 = gq0.z + x0.z, go0 = gq0.w + x0.w;
        float gi1 = gq1.x + x1.x, gf1 = gq1.y + x1.y, gg1 = gq1.z + x1.z, go1 = gq1.w + x1.w;

        int j0 = bx * 8 + cg * 2;
        // cell 0
        {
            float iv = 1.f / (1.f + expf(-gi0));
            float fv = 1.f / (1.f + expf(-gf0));
            float gv = tanhf(gg0);
            float ov = 1.f / (1.f + expf(-go0));
            float c = fv * g_cbuf[(size_t)b * HH + j0] + iv * gv;
            g_cbuf[(size_t)b * HH + j0] = c;
            float h = ov * tanhf(c);
            out[((size_t)b * SS + t) * HH + j0] = h;
            hTo[(size_t)j0 * BB + b] = h;
        }
        // cell 1
        {
            float iv = 1.f / (1.f + expf(-gi1));
            float fv = 1.f / (1.f + expf(-gf1));
            float gv = tanhf(gg1);
            float ov = 1.f / (1.f + expf(-go1));
            float c = fv * g_cbuf[(size_t)b * HH + j0 + 1] + iv * gv;
            g_cbuf[(size_t)b * HH + j0 + 1] = c;
            float h = ov * tanhf(c);
            out[((size_t)b * SS + t) * HH + j0 + 1] = h;
            hTo[(size_t)(j0 + 1) * BB + b] = h;
        }
    }
}

// ---------------- tail --------------------------------------------------------
__global__ void write_tail(float* __restrict__ out, long long hsz, int want_c) {
    int i = blockIdx.x * blockDim.x + threadIdx.x;
    if (i < BB * HH) {
        int b = i / HH, j = i % HH;
        out[hsz + i] = out[((size_t)b * SS + (SS - 1)) * HH + j];
        if (want_c) out[hsz + (long long)BB * HH + i] = g_cbuf[i];
    }
}

// ---------------- launch -------------------------------------------------------
extern "C" void kernel_launch(void* const* d_in, const int* in_sizes, int n_in,
                              void* d_out, int out_size) {
    const float* x  = (const float*)d_in[0];
    const float* h0 = (const float*)d_in[1];
    const float* c0 = (const float*)d_in[2];
    const float* Wi = (const float*)d_in[3];
    const float* bi = (const float*)d_in[4];
    const float* Wh = (const float*)d_in[5];
    const float* bh = (const float*)d_in[6];
    float* out = (float*)d_out;

    cudaFuncSetAttribute(lstm_step, cudaFuncAttributeMaxDynamicSharedMemorySize, 204800);

    init_state<<<(BB * HH + 255) / 256, 256>>>(h0, c0, bi, bh);
    prep_wh<<<(HH * GG) / 256, 256>>>(Wh);

    dim3 g1(GG / BN, (BB * SS) / BM);
    gemm_xg<<<g1, 256>>>(x, Wi);

    for (int t = 0; t < SS; t++) {
        lstm_step<<<128, 256, 204800>>>(out, t, t & 1);
    }

    long long hsz = (long long)BB * SS * HH;
    int want_h = ((long long)out_size >= hsz + (long long)BB * HH) ? 1 : 0;
    int want_c = ((long long)out_size >= hsz + 2LL * BB * HH) ? 1 : 0;
    if (want_h) {
        write_tail<<<(BB * HH + 255) / 256, 256>>>(out, hsz, want_c);
    }
}

// round 4
// speedup vs baseline: 1.7257x; 1.6023x over previous
#include <cuda_runtime.h>
#include <cuda_bf16.h>
#include <math.h>

#define BB 64
#define SS 512
#define DD 1024
#define HH 1024
#define GG 4096

typedef unsigned long long ull;
typedef unsigned int u32;

// ================= helpers =================
__device__ __forceinline__ ull ffma2(ull a, ull b, ull c) {
    ull d;
    asm("fma.rn.f32x2 %0, %1, %2, %3;" : "=l"(d) : "l"(a), "l"(b), "l"(c));
    return d;
}
__device__ __forceinline__ void cp_async16(unsigned s, const void* g) {
    asm volatile("cp.async.ca.shared.global [%0], [%1], 16;" :: "r"(s), "l"(g));
}
__device__ __forceinline__ void cp_commit() { asm volatile("cp.async.commit_group;"); }
template<int N> __device__ __forceinline__ void cp_wait() {
    asm volatile("cp.async.wait_group %0;" :: "n"(N));
}
__device__ __forceinline__ u32 smem_u32(const void* p) {
    u32 a;
    asm("{ .reg .u64 t; cvta.to.shared.u64 t, %1; cvt.u32.u64 %0, t; }" : "=r"(a) : "l"(p));
    return a;
}
__device__ __forceinline__ void ldsm_x4(u32 addr, u32& r0, u32& r1, u32& r2, u32& r3) {
    asm volatile("ldmatrix.sync.aligned.m8n8.x4.shared.b16 {%0,%1,%2,%3}, [%4];"
                 : "=r"(r0), "=r"(r1), "=r"(r2), "=r"(r3) : "r"(addr));
}
__device__ __forceinline__ void ldsm_x4t(u32 addr, u32& r0, u32& r1, u32& r2, u32& r3) {
    asm volatile("ldmatrix.sync.aligned.m8n8.x4.trans.shared.b16 {%0,%1,%2,%3}, [%4];"
                 : "=r"(r0), "=r"(r1), "=r"(r2), "=r"(r3) : "r"(addr));
}
__device__ __forceinline__ void mma16816(float* c, u32 a0, u32 a1, u32 a2, u32 a3, u32 b0, u32 b1) {
    asm volatile("mma.sync.aligned.m16n8k16.row.col.f32.bf16.bf16.f32 "
                 "{%0,%1,%2,%3},{%4,%5,%6,%7},{%8,%9},{%0,%1,%2,%3};"
                 : "+f"(c[0]), "+f"(c[1]), "+f"(c[2]), "+f"(c[3])
                 : "r"(a0), "r"(a1), "r"(a2), "r"(a3), "r"(b0), "r"(b1));
}

__host__ __device__ __forceinline__ int gmap(int p) { return (p & 3) * 1024 + (p >> 2); }

// ================= device scratch =================
__device__ float g_xg[(size_t)BB * SS * GG];                 // xg + (bi+bh), permuted cols
__device__ __nv_bfloat16 g_WhB[2][HH][GG];                   // [split][k][p]
__device__ __nv_bfloat16 g_hA[2][128][HH];                   // ping-pong A: rows 0..63 hi, 64..127 lo
__device__ float g_cbuf[BB * HH];
__device__ float g_bias[GG];

// ================= init =================
__global__ void init_state(const float* __restrict__ h0, const float* __restrict__ c0,
                           const float* __restrict__ bi, const float* __restrict__ bh) {
    int i = blockIdx.x * blockDim.x + threadIdx.x;
    if (i < BB * HH) {
        int j = i % HH;
        g_cbuf[i] = c0[j];
    }
    if (i < GG) {
        int g = gmap(i);
        g_bias[i] = bi[g] + bh[g];
    }
}

__global__ void init_hA(const float* __restrict__ h0) {
    int idx = blockIdx.x * blockDim.x + threadIdx.x;
    if (idx >= BB * HH) return;
    int b = idx >> 10, j = idx & 1023;
    float v = h0[j];
    __nv_bfloat16 hi = __float2bfloat16(v);
    __nv_bfloat16 lo = __float2bfloat16(v - __bfloat162float(hi));
    g_hA[0][b][j] = hi;
    g_hA[0][b + 64][j] = lo;
}

__global__ void prep_whB(const float* __restrict__ Wh) {
    int idx = blockIdx.x * blockDim.x + threadIdx.x;
    if (idx >= GG * HH) return;
    int k = idx >> 12, p = idx & 4095;
    float v = Wh[(size_t)gmap(p) * HH + k];
    __nv_bfloat16 hi = __float2bfloat16(v);
    __nv_bfloat16 lo = __float2bfloat16(v - __bfloat162float(hi));
    g_WhB[0][k][p] = hi;
    g_WhB[1][k][p] = lo;
}

// ================= input GEMM (f32x2, permuted cols) =================
#define BM 128
#define BN 128
#define BK 16

__global__ __launch_bounds__(256) void gemm_xg(const float* __restrict__ x,
                                               const float* __restrict__ Wi) {
    __shared__ float2 As2[BK][BM];
    __shared__ float  Bs[BK][BN];

    const int m0 = blockIdx.y * BM;
    const int n0 = blockIdx.x * BN;
    const int tid = threadIdx.x;
    const int tx = tid % 16;
    const int ty = tid / 16;
    const int lr = tid / 4;
    const int lk = (tid % 4) * 4;

    const int g1 = gmap(n0 + lr);
    const int g2 = gmap(n0 + lr + 64);

    ull acc[8][4];
#pragma unroll
    for (int i = 0; i < 8; i++)
#pragma unroll
        for (int j = 0; j < 4; j++) acc[i][j] = 0ULL;

    for (int k0 = 0; k0 < DD; k0 += BK) {
        float4 a0 = *(const float4*)&x[(size_t)(m0 + lr) * DD + k0 + lk];
        float4 a1 = *(const float4*)&x[(size_t)(m0 + lr + 64) * DD + k0 + lk];
        float4 b0 = *(const float4*)&Wi[(size_t)g1 * DD + k0 + lk];
        float4 b1 = *(const float4*)&Wi[(size_t)g2 * DD + k0 + lk];
        As2[lk + 0][lr] = make_float2(a0.x, a0.x);
        As2[lk + 1][lr] = make_float2(a0.y, a0.y);
        As2[lk + 2][lr] = make_float2(a0.z, a0.z);
        As2[lk + 3][lr] = make_float2(a0.w, a0.w);
        As2[lk + 0][lr + 64] = make_float2(a1.x, a1.x);
        As2[lk + 1][lr + 64] = make_float2(a1.y, a1.y);
        As2[lk + 2][lr + 64] = make_float2(a1.z, a1.z);
        As2[lk + 3][lr + 64] = make_float2(a1.w, a1.w);
        Bs[lk + 0][lr] = b0.x; Bs[lk + 1][lr] = b0.y;
        Bs[lk + 2][lr] = b0.z; Bs[lk + 3][lr] = b0.w;
        Bs[lk + 0][lr + 64] = b1.x; Bs[lk + 1][lr + 64] = b1.y;
        Bs[lk + 2][lr + 64] = b1.z; Bs[lk + 3][lr + 64] = b1.w;
        __syncthreads();

#pragma unroll
        for (int kk = 0; kk < BK; kk++) {
            const ull* ap = (const ull*)&As2[kk][ty * 8];
            ulonglong2 A0 = *(const ulonglong2*)(ap);
            ulonglong2 A1 = *(const ulonglong2*)(ap + 2);
            ulonglong2 A2 = *(const ulonglong2*)(ap + 4);
            ulonglong2 A3 = *(const ulonglong2*)(ap + 6);
            const ull* bp = (const ull*)&Bs[kk][tx * 8];
            ulonglong2 B0 = *(const ulonglong2*)(bp);
            ulonglong2 B1 = *(const ulonglong2*)(bp + 2);
            ull a[8] = {A0.x, A0.y, A1.x, A1.y, A2.x, A2.y, A3.x, A3.y};
            ull b[4] = {B0.x, B0.y, B1.x, B1.y};
#pragma unroll
            for (int i = 0; i < 8; i++)
#pragma unroll
                for (int j = 0; j < 4; j++) acc[i][j] = ffma2(a[i], b[j], acc[i][j]);
        }
        __syncthreads();
    }

    const int bc = n0 + tx * 8;
    float4 bv0 = *(const float4*)&g_bias[bc];
    float4 bv1 = *(const float4*)&g_bias[bc + 4];
    float bias[8] = {bv0.x, bv0.y, bv0.z, bv0.w, bv1.x, bv1.y, bv1.z, bv1.w};
#pragma unroll
    for (int i = 0; i < 8; i++) {
        int m = m0 + ty * 8 + i;
        float* dst = &g_xg[(size_t)m * GG + bc];
#pragma unroll
        for (int j = 0; j < 4; j++) {
            float2 v = *(float2*)&acc[i][j];
            dst[2 * j] = v.x + bias[2 * j];
            dst[2 * j + 1] = v.y + bias[2 * j + 1];
        }
    }
}

// ================= mma.sync recurrent step =================
// 128 CTAs x 256 threads. CTA s owns 32 permuted cols [s*32..) = hidden j in [s*8, s*8+8).
// A = [h_hi; h_lo] (M=128), 2 B passes (hi, lo) into fp32 regs. gate = D[b] + D[b+64] + xg.

// smem offsets (bytes). A rows padded to 144B (64 bf16 + 8 pad), B rows 80B (32 bf16 + 8 pad).
#define A0OFF 0
#define A1OFF 18432
#define B0OFF 36864
#define B1OFF 47104
#define DSOFF 57344
#define DS_STRIDE 36
#define STEP_SMEM 75776

extern __shared__ char smx[];

__device__ __forceinline__ void load_tiles(u32 sb, int buf, int k0, int ping, int c0, int tid) {
    const u32 abase = sb + (buf ? A1OFF : A0OFF);
    const __nv_bfloat16* aflat = &g_hA[ping][0][0];
#pragma unroll
    for (int i = 0; i < 4; i++) {
        int o = tid + i * 256;            // 0..1023
        int row = o >> 3, seg = o & 7;
        cp_async16(abase + row * 144 + seg * 16,
                   (const char*)(aflat + (size_t)row * HH + k0) + seg * 16);
    }
    const u32 bbase = sb + (buf ? B1OFF : B0OFF);
#pragma unroll
    for (int i = 0; i < 2; i++) {
        int o = tid + i * 256;            // 0..511
        int sp = o >> 8, rr = (o & 255) >> 2, seg = o & 3;
        cp_async16(bbase + sp * 5120 + rr * 80 + seg * 16,
                   (const char*)(&g_WhB[sp][k0 + rr][c0]) + seg * 16);
    }
    cp_commit();
}

__global__ __launch_bounds__(256, 1) void lstm_step(float* __restrict__ out, int t) {
    const int tid = threadIdx.x;
    const int wid = tid >> 5, lane = tid & 31;
    const int wm = wid & 3, wn = wid >> 2;
    const int s = blockIdx.x;
    const int c0 = s * 32;
    const int j0 = s * 8;
    const int ping = t & 1;
    const u32 sb = smem_u32(smx);
    float* Ds = (float*)(smx + DSOFF);

    float acc[2][2][4];
#pragma unroll
    for (int a = 0; a < 2; a++)
#pragma unroll
        for (int b = 0; b < 2; b++)
#pragma unroll
            for (int q = 0; q < 4; q++) acc[a][b][q] = 0.f;

    load_tiles(sb, 0, 0, ping, c0, tid);

    const u32 a_row = wm * 32 + (lane & 15);
    const u32 a_half = (lane >> 4) * 16;
    const u32 b_r = (lane & 15);
    const u32 b_cb = (wn * 16 + (lane >> 4) * 8) * 2;

    for (int cc = 0; cc < 16; cc++) {
        if (cc < 15) load_tiles(sb, (cc + 1) & 1, (cc + 1) * 64, ping, c0, tid);
        if (cc < 15) { cp_wait<1>(); } else { cp_wait<0>(); }
        __syncthreads();

        const u32 Ab = sb + ((cc & 1) ? A1OFF : A0OFF);
        const u32 Bb = sb + ((cc & 1) ? B1OFF : B0OFF);
#pragma unroll
        for (int kk = 0; kk < 4; kk++) {
            u32 a0, a1, a2, a3, a4, a5, a6, a7;
            u32 aaddr = Ab + a_row * 144 + kk * 32 + a_half;
            ldsm_x4(aaddr, a0, a1, a2, a3);
            ldsm_x4(aaddr + 16 * 144, a4, a5, a6, a7);
            u32 b0, b1, b2, b3, b4, b5, b6, b7;
            u32 baddr = Bb + (kk * 16 + b_r) * 80 + b_cb;
            ldsm_x4t(baddr, b0, b1, b2, b3);
            ldsm_x4t(baddr + 5120, b4, b5, b6, b7);
            mma16816(acc[0][0], a0, a1, a2, a3, b0, b1);
            mma16816(acc[0][1], a0, a1, a2, a3, b2, b3);
            mma16816(acc[1][0], a4, a5, a6, a7, b0, b1);
            mma16816(acc[1][1], a4, a5, a6, a7, b2, b3);
            mma16816(acc[0][0], a0, a1, a2, a3, b4, b5);
            mma16816(acc[0][1], a0, a1, a2, a3, b6, b7);
            mma16816(acc[1][0], a4, a5, a6, a7, b4, b5);
            mma16816(acc[1][1], a4, a5, a6, a7, b6, b7);
        }
        __syncthreads();
    }

    // dump accumulators to Ds[128][36]
    {
        const int g = lane >> 2, tq = lane & 3;
#pragma unroll
        for (int mt = 0; mt < 2; mt++)
#pragma unroll
            for (int nt = 0; nt < 2; nt++) {
                int r = wm * 32 + mt * 16 + g;
                int c = wn * 16 + nt * 8 + tq * 2;
                *(float2*)&Ds[r * DS_STRIDE + c] = make_float2(acc[mt][nt][0], acc[mt][nt][1]);
                *(float2*)&Ds[(r + 8) * DS_STRIDE + c] = make_float2(acc[mt][nt][2], acc[mt][nt][3]);
            }
    }
    __syncthreads();

    // epilogue: thread b (0..63) handles 8 hidden units
    if (tid < 64) {
        const int b = tid;
        const float* dh = Ds + b * DS_STRIDE;
        const float* dl = Ds + (b + 64) * DS_STRIDE;
        const float* xrow = g_xg + ((size_t)b * SS + t) * GG + c0;
        float* crow = g_cbuf + (size_t)b * HH + j0;
        float hv[8];
        __nv_bfloat16 hib[8], lob[8];
#pragma unroll
        for (int jj = 0; jj < 8; jj++) {
            float gi = dh[jj * 4 + 0] + dl[jj * 4 + 0] + xrow[jj * 4 + 0];
            float gf = dh[jj * 4 + 1] + dl[jj * 4 + 1] + xrow[jj * 4 + 1];
            float gg = dh[jj * 4 + 2] + dl[jj * 4 + 2] + xrow[jj * 4 + 2];
            float go = dh[jj * 4 + 3] + dl[jj * 4 + 3] + xrow[jj * 4 + 3];
            float iv = 1.f / (1.f + expf(-gi));
            float fv = 1.f / (1.f + expf(-gf));
            float gv = tanhf(gg);
            float ov = 1.f / (1.f + expf(-go));
            float c = fv * crow[jj] + iv * gv;
            crow[jj] = c;
            float h = ov * tanhf(c);
            hv[jj] = h;
            __nv_bfloat16 hi = __float2bfloat16(h);
            hib[jj] = hi;
            lob[jj] = __float2bfloat16(h - __bfloat162float(hi));
        }
        float* orow = out + ((size_t)b * SS + t) * HH + j0;
#pragma unroll
        for (int q = 0; q < 2; q++)
            *(float4*)(orow + q * 4) = make_float4(hv[q * 4], hv[q * 4 + 1], hv[q * 4 + 2], hv[q * 4 + 3]);
        *(float4*)&g_hA[ping ^ 1][b][j0] = *(float4*)hib;
        *(float4*)&g_hA[ping ^ 1][b + 64][j0] = *(float4*)lob;
    }
}

// ================= tail =================
__global__ void write_tail(float* __restrict__ out, long long hsz, int want_c) {
    int i = blockIdx.x * blockDim.x + threadIdx.x;
    if (i < BB * HH) {
        int b = i / HH, j = i % HH;
        out[hsz + i] = out[((size_t)b * SS + (SS - 1)) * HH + j];
        if (want_c) out[hsz + (long long)BB * HH + i] = g_cbuf[i];
    }
}

// ================= launch =================
extern "C" void kernel_launch(void* const* d_in, const int* in_sizes, int n_in,
                              void* d_out, int out_size) {
    const float* x  = (const float*)d_in[0];
    const float* h0 = (const float*)d_in[1];
    const float* c0 = (const float*)d_in[2];
    const float* Wi = (const float*)d_in[3];
    const float* bi = (const float*)d_in[4];
    const float* Wh = (const float*)d_in[5];
    const float* bh = (const float*)d_in[6];
    float* out = (float*)d_out;

    cudaFuncSetAttribute(lstm_step, cudaFuncAttributeMaxDynamicSharedMemorySize, STEP_SMEM);

    init_state<<<(BB * HH + 255) / 256, 256>>>(h0, c0, bi, bh);
    init_hA<<<(BB * HH + 255) / 256, 256>>>(h0);
    prep_whB<<<(GG * HH) / 256, 256>>>(Wh);

    dim3 g1(GG / BN, (BB * SS) / BM);
    gemm_xg<<<g1, 256>>>(x, Wi);

    for (int t = 0; t < SS; t++) {
        lstm_step<<<128, 256, STEP_SMEM>>>(out, t);
    }

    long long hsz = (long long)BB * SS * HH;
    int want_h = ((long long)out_size >= hsz + (long long)BB * HH) ? 1 : 0;
    int want_c = ((long long)out_size >= hsz + 2LL * BB * HH) ? 1 : 0;
    if (want_h) {
        write_tail<<<(BB * HH + 255) / 256, 256>>>(out, hsz, want_c);
    }
}

// round 5
// speedup vs baseline: 3.3554x; 1.9443x over previous
#include <cuda_runtime.h>
#include <cuda_bf16.h>
#include <math.h>

#define BB 64
#define SS 512
#define DD 1024
#define HH 1024
#define GG 4096

typedef unsigned int u32;

// ================= helpers =================
__device__ __forceinline__ void cp_async16(unsigned s, const void* g) {
    asm volatile("cp.async.ca.shared.global [%0], [%1], 16;" :: "r"(s), "l"(g));
}
__device__ __forceinline__ void cp_async16_cg(unsigned s, const void* g) {
    asm volatile("cp.async.cg.shared.global [%0], [%1], 16;" :: "r"(s), "l"(g));
}
__device__ __forceinline__ void cp_commit() { asm volatile("cp.async.commit_group;"); }
template<int N> __device__ __forceinline__ void cp_wait() {
    asm volatile("cp.async.wait_group %0;" :: "n"(N));
}
__device__ __forceinline__ u32 smem_u32(const void* p) {
    u32 a;
    asm("{ .reg .u64 t; cvta.to.shared.u64 t, %1; cvt.u32.u64 %0, t; }" : "=r"(a) : "l"(p));
    return a;
}
__device__ __forceinline__ void ldsm_x4(u32 addr, u32& r0, u32& r1, u32& r2, u32& r3) {
    asm volatile("ldmatrix.sync.aligned.m8n8.x4.shared.b16 {%0,%1,%2,%3}, [%4];"
                 : "=r"(r0), "=r"(r1), "=r"(r2), "=r"(r3) : "r"(addr));
}
__device__ __forceinline__ void ldsm_x4t(u32 addr, u32& r0, u32& r1, u32& r2, u32& r3) {
    asm volatile("ldmatrix.sync.aligned.m8n8.x4.trans.shared.b16 {%0,%1,%2,%3}, [%4];"
                 : "=r"(r0), "=r"(r1), "=r"(r2), "=r"(r3) : "r"(addr));
}
__device__ __forceinline__ void mma16816(float* c, u32 a0, u32 a1, u32 a2, u32 a3, u32 b0, u32 b1) {
    asm volatile("mma.sync.aligned.m16n8k16.row.col.f32.bf16.bf16.f32 "
                 "{%0,%1,%2,%3},{%4,%5,%6,%7},{%8,%9},{%0,%1,%2,%3};"
                 : "+f"(c[0]), "+f"(c[1]), "+f"(c[2]), "+f"(c[3])
                 : "r"(a0), "r"(a1), "r"(a2), "r"(a3), "r"(b0), "r"(b1));
}

__host__ __device__ __forceinline__ int gmap(int p) { return (p & 3) * 1024 + (p >> 2); }

// ================= device scratch =================
__device__ float g_xg[(size_t)BB * SS * GG];                 // [t][b][p] xg + bias, permuted cols
__device__ __nv_bfloat16 g_xA[2][(size_t)BB * SS * DD];      // x hi/lo bf16
__device__ __nv_bfloat16 g_WiB[2][DD][GG];                   // Wi hi/lo, k-major, permuted cols
__device__ __nv_bfloat16 g_WhB[2][HH][GG];                   // Wh hi/lo, k-major, permuted cols
__device__ __nv_bfloat16 g_hA[2][128][HH];                   // ping-pong h: rows 0..63 hi, 64..127 lo
__device__ float g_cbuf[BB * HH];
__device__ float g_bias[GG];
__device__ int g_count;
__device__ int g_gen;

// ================= init / prep =================
__global__ void init_state(const float* __restrict__ h0, const float* __restrict__ c0,
                           const float* __restrict__ bi, const float* __restrict__ bh) {
    int i = blockIdx.x * blockDim.x + threadIdx.x;
    if (i == 0) { g_count = 0; g_gen = 0; }
    if (i < BB * HH) {
        int j = i % HH;
        g_cbuf[i] = c0[j];
    }
    if (i < GG) {
        int g = gmap(i);
        g_bias[i] = bi[g] + bh[g];
    }
}

__global__ void init_hA(const float* __restrict__ h0) {
    int idx = blockIdx.x * blockDim.x + threadIdx.x;
    if (idx >= BB * HH) return;
    int b = idx >> 10, j = idx & 1023;
    float v = h0[j];
    __nv_bfloat16 hi = __float2bfloat16(v);
    __nv_bfloat16 lo = __float2bfloat16(v - __bfloat162float(hi));
    g_hA[0][b][j] = hi;
    g_hA[0][b + 64][j] = lo;
}

__global__ void prep_whB(const float* __restrict__ Wh) {
    int idx = blockIdx.x * blockDim.x + threadIdx.x;
    if (idx >= GG * HH) return;
    int k = idx >> 12, p = idx & 4095;
    float v = Wh[(size_t)gmap(p) * HH + k];
    __nv_bfloat16 hi = __float2bfloat16(v);
    __nv_bfloat16 lo = __float2bfloat16(v - __bfloat162float(hi));
    g_WhB[0][k][p] = hi;
    g_WhB[1][k][p] = lo;
}

__global__ void prep_wiB(const float* __restrict__ Wi) {
    int idx = blockIdx.x * blockDim.x + threadIdx.x;
    if (idx >= GG * DD) return;
    int k = idx >> 12, p = idx & 4095;
    float v = Wi[(size_t)gmap(p) * DD + k];
    __nv_bfloat16 hi = __float2bfloat16(v);
    __nv_bfloat16 lo = __float2bfloat16(v - __bfloat162float(hi));
    g_WiB[0][k][p] = hi;
    g_WiB[1][k][p] = lo;
}

__global__ void prep_xA(const float* __restrict__ x) {
    size_t idx = (size_t)blockIdx.x * blockDim.x + threadIdx.x;
    if (idx >= (size_t)BB * SS * DD) return;
    float v = x[idx];
    __nv_bfloat16 hi = __float2bfloat16(v);
    __nv_bfloat16 lo = __float2bfloat16(v - __bfloat162float(hi));
    g_xA[0][idx] = hi;
    g_xA[1][idx] = lo;
}

// ================= input GEMM via mma.sync (split-2 bf16) =================
// Tile: 64 real M rows (stacked hi/lo -> 128), N=128, K chunks of 64.
// 8 warps = 4(M) x 2(N). Grid = (4096/128) x (32768/64).

#define GA0 0
#define GA1 18432
#define GB0 36864
#define GB1 71680
#define GDS 106496
#define GEMM_SMEM 140288

extern __shared__ char smx[];

__device__ __forceinline__ void g_loadA(u32 dst, int m0, int k0, int tid) {
#pragma unroll
    for (int i = 0; i < 4; i++) {
        int o = tid + i * 256;
        int row = o >> 3, seg = o & 7;
        int sp = row >> 6, srow = m0 + (row & 63);
        cp_async16(dst + row * 144 + seg * 16,
                   (const char*)(&g_xA[sp][0] + (size_t)srow * DD + k0) + seg * 16);
    }
}
__device__ __forceinline__ void g_loadB(u32 dst, int n0, int k0, int tid) {
#pragma unroll
    for (int i = 0; i < 8; i++) {
        int o = tid + i * 256;
        int sp = o >> 10, r = (o & 1023) >> 4, seg = o & 15;
        cp_async16(dst + sp * 17408 + r * 272 + seg * 16,
                   (const char*)(&g_WiB[sp][k0 + r][n0]) + seg * 16);
    }
}

__global__ __launch_bounds__(256, 1) void gemm_xg_mma() {
    const int tid = threadIdx.x;
    const int wid = tid >> 5, lane = tid & 31;
    const int wm = wid & 3, wn = wid >> 2;
    const int n0 = blockIdx.x * 128;
    const int m0 = blockIdx.y * 64;
    const u32 sb = smem_u32(smx);
    float* Ds = (float*)(smx + GDS);

    float acc[2][8][4];
#pragma unroll
    for (int a = 0; a < 2; a++)
#pragma unroll
        for (int b = 0; b < 8; b++)
#pragma unroll
            for (int q = 0; q < 4; q++) acc[a][b][q] = 0.f;

    g_loadA(sb + GA0, m0, 0, tid);
    g_loadB(sb + GB0, n0, 0, tid);
    cp_commit();

    const u32 a_row = wm * 32 + (lane & 15);
    const u32 a_half = (lane >> 4) * 16;
    const u32 b_r = (lane & 15);
    const u32 b_coff = (lane >> 4) * 16;

    for (int cc = 0; cc < 16; cc++) {
        if (cc < 15) {
            g_loadA(sb + (((cc + 1) & 1) ? GA1 : GA0), m0, (cc + 1) * 64, tid);
            g_loadB(sb + (((cc + 1) & 1) ? GB1 : GB0), n0, (cc + 1) * 64, tid);
            cp_commit();
            cp_wait<1>();
        } else {
            cp_wait<0>();
        }
        __syncthreads();

        const u32 Ab = sb + ((cc & 1) ? GA1 : GA0);
        const u32 Bb = sb + ((cc & 1) ? GB1 : GB0);
#pragma unroll
        for (int kk = 0; kk < 4; kk++) {
            u32 a0, a1, a2, a3, a4, a5, a6, a7;
            u32 aaddr = Ab + a_row * 144 + kk * 32 + a_half;
            ldsm_x4(aaddr, a0, a1, a2, a3);
            ldsm_x4(aaddr + 16 * 144, a4, a5, a6, a7);
#pragma unroll
            for (int sp = 0; sp < 2; sp++) {
                const u32 Bb2 = Bb + sp * 17408;
#pragma unroll
                for (int nt = 0; nt < 4; nt++) {
                    u32 b0, b1, b2, b3;
                    u32 baddr = Bb2 + (kk * 16 + b_r) * 272 + (wn * 64 + nt * 16) * 2 + b_coff;
                    ldsm_x4t(baddr, b0, b1, b2, b3);
                    mma16816(acc[0][nt * 2], a0, a1, a2, a3, b0, b1);
                    mma16816(acc[0][nt * 2 + 1], a0, a1, a2, a3, b2, b3);
                    mma16816(acc[1][nt * 2], a4, a5, a6, a7, b0, b1);
                    mma16816(acc[1][nt * 2 + 1], a4, a5, a6, a7, b2, b3);
                }
            }
        }
        __syncthreads();
    }

    const int g = lane >> 2, tq = lane & 3;
    if (wm >= 2) {
        // lo rows -> Ds[real_row][col]
#pragma unroll
        for (int mt = 0; mt < 2; mt++)
#pragma unroll
            for (int nt = 0; nt < 8; nt++) {
                int r = (wm - 2) * 32 + mt * 16 + g;
                int c = wn * 64 + nt * 8 + tq * 2;
                *(float2*)&Ds[r * 132 + c] = make_float2(acc[mt][nt][0], acc[mt][nt][1]);
                *(float2*)&Ds[(r + 8) * 132 + c] = make_float2(acc[mt][nt][2], acc[mt][nt][3]);
            }
    }
    __syncthreads();
    if (wm < 2) {
#pragma unroll
        for (int mt = 0; mt < 2; mt++)
#pragma unroll
            for (int nt = 0; nt < 8; nt++) {
                int m = wm * 32 + mt * 16 + g;
                int c = wn * 64 + nt * 8 + tq * 2;
                float bz0 = g_bias[n0 + c], bz1 = g_bias[n0 + c + 1];
                {
                    float v0 = acc[mt][nt][0] + Ds[m * 132 + c] + bz0;
                    float v1 = acc[mt][nt][1] + Ds[m * 132 + c + 1] + bz1;
                    int mg = m0 + m, bb = mg >> 9, tt = mg & 511;
                    *(float2*)&g_xg[((size_t)tt * BB + bb) * GG + n0 + c] = make_float2(v0, v1);
                }
                {
                    int m2 = m + 8;
                    float v0 = acc[mt][nt][2] + Ds[m2 * 132 + c] + bz0;
                    float v1 = acc[mt][nt][3] + Ds[m2 * 132 + c + 1] + bz1;
                    int mg = m0 + m2, bb = mg >> 9, tt = mg & 511;
                    *(float2*)&g_xg[((size_t)tt * BB + bb) * GG + n0 + c] = make_float2(v0, v1);
                }
            }
    }
}

// ================= persistent recurrent kernel =================
// 128 CTAs (1/SM), 256 threads. CTA s owns 32 permuted cols (8 hidden units).
// Wh (hi+lo, 160KB) resident in SMEM for all 512 steps. Software grid barrier.

#define PB 0
#define PA0 163840
#define PA1 182272
#define PDS 200704
#define PERSIST_SMEM 219136

__device__ __forceinline__ void p_loadA(u32 dst, const __nv_bfloat16* hA, int k0, int tid) {
#pragma unroll
    for (int i = 0; i < 4; i++) {
        int o = tid + i * 256;
        int row = o >> 3, seg = o & 7;
        cp_async16_cg(dst + row * 144 + seg * 16,
                      (const char*)(hA + (size_t)row * HH + k0) + seg * 16);
    }
    cp_commit();
}

__global__ __launch_bounds__(256, 1) void lstm_persist(float* __restrict__ out) {
    const int tid = threadIdx.x;
    const int wid = tid >> 5, lane = tid & 31;
    const int wm = wid & 3, wn = wid >> 2;
    const int s = blockIdx.x;
    const int c0 = s * 32;
    const int j0 = s * 8;
    const u32 sb = smem_u32(smx);
    float* Ds = (float*)(smx + PDS);

    // ---- load Wh tiles once (hi at +0, lo at +81920), ldsm rows of 80B ----
#pragma unroll
    for (int i = 0; i < 32; i++) {
        int o = tid + i * 256;            // 0..8191
        int sp = o >> 12;
        int rem = o & 4095;
        int k = rem >> 2, seg = rem & 3;
        cp_async16(sb + PB + sp * 81920 + k * 80 + seg * 16,
                   (const char*)(&g_WhB[sp][k][c0]) + seg * 16);
    }
    cp_commit();
    cp_wait<0>();
    __syncthreads();

    // ---- cell state in registers ----
    const int eb = tid >> 1, eh = tid & 1;
    float cr[4];
    if (tid < 128) {
#pragma unroll
        for (int q = 0; q < 4; q++) cr[q] = g_cbuf[(size_t)eb * HH + j0 + eh * 4 + q];
    }

    const u32 a_row = wm * 32 + (lane & 15);
    const u32 a_half = (lane >> 4) * 16;
    const u32 b_r = (lane & 15);
    const u32 b_cb = (wn * 16 + (lane >> 4) * 8) * 2;

    for (int t = 0; t < SS; t++) {
        const int ping = t & 1;
        const __nv_bfloat16* hA = &g_hA[ping][0][0];

        float acc[2][2][4];
#pragma unroll
        for (int a = 0; a < 2; a++)
#pragma unroll
            for (int b = 0; b < 2; b++)
#pragma unroll
                for (int q = 0; q < 4; q++) acc[a][b][q] = 0.f;

        p_loadA(sb + PA0, hA, 0, tid);

        for (int cc = 0; cc < 16; cc++) {
            if (cc < 15) {
                p_loadA(sb + (((cc + 1) & 1) ? PA1 : PA0), hA, (cc + 1) * 64, tid);
                cp_wait<1>();
            } else {
                cp_wait<0>();
            }
            __syncthreads();

            const u32 Ab = sb + ((cc & 1) ? PA1 : PA0);
#pragma unroll
            for (int kk = 0; kk < 4; kk++) {
                u32 a0, a1, a2, a3, a4, a5, a6, a7;
                u32 aaddr = Ab + a_row * 144 + kk * 32 + a_half;
                ldsm_x4(aaddr, a0, a1, a2, a3);
                ldsm_x4(aaddr + 16 * 144, a4, a5, a6, a7);
                u32 b0, b1, b2, b3, b4, b5, b6, b7;
                u32 baddr = sb + PB + (cc * 64 + kk * 16 + b_r) * 80 + b_cb;
                ldsm_x4t(baddr, b0, b1, b2, b3);
                ldsm_x4t(baddr + 81920, b4, b5, b6, b7);
                mma16816(acc[0][0], a0, a1, a2, a3, b0, b1);
                mma16816(acc[0][1], a0, a1, a2, a3, b2, b3);
                mma16816(acc[1][0], a4, a5, a6, a7, b0, b1);
                mma16816(acc[1][1], a4, a5, a6, a7, b2, b3);
                mma16816(acc[0][0], a0, a1, a2, a3, b4, b5);
                mma16816(acc[0][1], a0, a1, a2, a3, b6, b7);
                mma16816(acc[1][0], a4, a5, a6, a7, b4, b5);
                mma16816(acc[1][1], a4, a5, a6, a7, b6, b7);
            }
            __syncthreads();
        }

        // dump accumulators to Ds[128][36]
        {
            const int g = lane >> 2, tq = lane & 3;
#pragma unroll
            for (int mt = 0; mt < 2; mt++)
#pragma unroll
                for (int nt = 0; nt < 2; nt++) {
                    int r = wm * 32 + mt * 16 + g;
                    int c = wn * 16 + nt * 8 + tq * 2;
                    *(float2*)&Ds[r * 36 + c] = make_float2(acc[mt][nt][0], acc[mt][nt][1]);
                    *(float2*)&Ds[(r + 8) * 36 + c] = make_float2(acc[mt][nt][2], acc[mt][nt][3]);
                }
        }
        __syncthreads();

        // epilogue: 128 threads, 4 hidden units each
        if (tid < 128) {
            const float* dh = Ds + eb * 36 + eh * 16;
            const float* dl = Ds + (eb + 64) * 36 + eh * 16;
            const float* xr = g_xg + ((size_t)t * BB + eb) * GG + c0 + eh * 16;
            float hv[4];
            __nv_bfloat16 hib[4], lob[4];
#pragma unroll
            for (int q = 0; q < 4; q++) {
                float gi = dh[q * 4 + 0] + dl[q * 4 + 0] + xr[q * 4 + 0];
                float gf = dh[q * 4 + 1] + dl[q * 4 + 1] + xr[q * 4 + 1];
                float gg = dh[q * 4 + 2] + dl[q * 4 + 2] + xr[q * 4 + 2];
                float go = dh[q * 4 + 3] + dl[q * 4 + 3] + xr[q * 4 + 3];
                float iv = 1.f / (1.f + expf(-gi));
                float fv = 1.f / (1.f + expf(-gf));
                float gv = tanhf(gg);
                float ov = 1.f / (1.f + expf(-go));
                float c = fv * cr[q] + iv * gv;
                cr[q] = c;
                float h = ov * tanhf(c);
                hv[q] = h;
                __nv_bfloat16 hi = __float2bfloat16(h);
                hib[q] = hi;
                lob[q] = __float2bfloat16(h - __bfloat162float(hi));
            }
            *(float4*)&out[((size_t)eb * SS + t) * HH + j0 + eh * 4] =
                make_float4(hv[0], hv[1], hv[2], hv[3]);
            *(uint2*)&g_hA[ping ^ 1][eb][j0 + eh * 4] = *(uint2*)hib;
            *(uint2*)&g_hA[ping ^ 1][eb + 64][j0 + eh * 4] = *(uint2*)lob;
        }

        // ---- grid barrier ----
        __threadfence();
        __syncthreads();
        if (tid == 0) {
            if (atomicAdd(&g_count, 1) == 127) {
                g_count = 0;
                __threadfence();
                atomicExch(&g_gen, t + 1);
            } else {
                while (*(volatile int*)&g_gen < t + 1) __nanosleep(32);
            }
            __threadfence();
        }
        __syncthreads();
    }

    if (tid < 128) {
#pragma unroll
        for (int q = 0; q < 4; q++) g_cbuf[(size_t)eb * HH + j0 + eh * 4 + q] = cr[q];
    }
}

// ================= tail =================
__global__ void write_tail(float* __restrict__ out, long long hsz, int want_c) {
    int i = blockIdx.x * blockDim.x + threadIdx.x;
    if (i < BB * HH) {
        int b = i / HH, j = i % HH;
        out[hsz + i] = out[((size_t)b * SS + (SS - 1)) * HH + j];
        if (want_c) out[hsz + (long long)BB * HH + i] = g_cbuf[i];
    }
}

// ================= launch =================
extern "C" void kernel_launch(void* const* d_in, const int* in_sizes, int n_in,
                              void* d_out, int out_size) {
    const float* x  = (const float*)d_in[0];
    const float* h0 = (const float*)d_in[1];
    const float* c0 = (const float*)d_in[2];
    const float* Wi = (const float*)d_in[3];
    const float* bi = (const float*)d_in[4];
    const float* Wh = (const float*)d_in[5];
    const float* bh = (const float*)d_in[6];
    float* out = (float*)d_out;

    cudaFuncSetAttribute(gemm_xg_mma, cudaFuncAttributeMaxDynamicSharedMemorySize, GEMM_SMEM);
    cudaFuncSetAttribute(lstm_persist, cudaFuncAttributeMaxDynamicSharedMemorySize, PERSIST_SMEM);

    init_state<<<(BB * HH + 255) / 256, 256>>>(h0, c0, bi, bh);
    init_hA<<<(BB * HH + 255) / 256, 256>>>(h0);
    prep_whB<<<(GG * HH) / 256, 256>>>(Wh);
    prep_wiB<<<(GG * DD) / 256, 256>>>(Wi);
    prep_xA<<<(int)(((size_t)BB * SS * DD) / 256), 256>>>(x);

    dim3 gg(GG / 128, (BB * SS) / 64);
    gemm_xg_mma<<<gg, 256, GEMM_SMEM>>>();

    lstm_persist<<<128, 256, PERSIST_SMEM>>>(out);

    long long hsz = (long long)BB * SS * HH;
    int want_h = ((long long)out_size >= hsz + (long long)BB * HH) ? 1 : 0;
    int want_c = ((long long)out_size >= hsz + 2LL * BB * HH) ? 1 : 0;
    if (want_h) {
        write_tail<<<(BB * HH + 255) / 256, 256>>>(out, hsz, want_c);
    }
}

// round 6
// speedup vs baseline: 4.1417x; 1.2343x over previous
#include <cuda_runtime.h>
#include <cuda_bf16.h>
#include <math.h>

#define BB 64
#define SS 512
#define DD 1024
#define HH 1024
#define GG 4096

typedef unsigned int u32;

// ================= helpers =================
__device__ __forceinline__ void cp_async16(unsigned s, const void* g) {
    asm volatile("cp.async.ca.shared.global [%0], [%1], 16;" :: "r"(s), "l"(g));
}
__device__ __forceinline__ void cp_async16_cg(unsigned s, const void* g) {
    asm volatile("cp.async.cg.shared.global [%0], [%1], 16;" :: "r"(s), "l"(g));
}
__device__ __forceinline__ void cp_commit() { asm volatile("cp.async.commit_group;"); }
template<int N> __device__ __forceinline__ void cp_wait() {
    asm volatile("cp.async.wait_group %0;" :: "n"(N));
}
__device__ __forceinline__ u32 smem_u32(const void* p) {
    u32 a;
    asm("{ .reg .u64 t; cvta.to.shared.u64 t, %1; cvt.u32.u64 %0, t; }" : "=r"(a) : "l"(p));
    return a;
}
__device__ __forceinline__ void ldsm_x4(u32 addr, u32& r0, u32& r1, u32& r2, u32& r3) {
    asm volatile("ldmatrix.sync.aligned.m8n8.x4.shared.b16 {%0,%1,%2,%3}, [%4];"
                 : "=r"(r0), "=r"(r1), "=r"(r2), "=r"(r3) : "r"(addr));
}
__device__ __forceinline__ void ldsm_x4t(u32 addr, u32& r0, u32& r1, u32& r2, u32& r3) {
    asm volatile("ldmatrix.sync.aligned.m8n8.x4.trans.shared.b16 {%0,%1,%2,%3}, [%4];"
                 : "=r"(r0), "=r"(r1), "=r"(r2), "=r"(r3) : "r"(addr));
}
__device__ __forceinline__ void mma16816(float* c, u32 a0, u32 a1, u32 a2, u32 a3, u32 b0, u32 b1) {
    asm volatile("mma.sync.aligned.m16n8k16.row.col.f32.bf16.bf16.f32 "
                 "{%0,%1,%2,%3},{%4,%5,%6,%7},{%8,%9},{%0,%1,%2,%3};"
                 : "+f"(c[0]), "+f"(c[1]), "+f"(c[2]), "+f"(c[3])
                 : "r"(a0), "r"(a1), "r"(a2), "r"(a3), "r"(b0), "r"(b1));
}
__device__ __forceinline__ u32 ld_acq(const u32* p) {
    u32 v;
    asm volatile("ld.acquire.gpu.global.u32 %0, [%1];" : "=r"(v) : "l"(p) : "memory");
    return v;
}
__device__ __forceinline__ void red_release(u32* p) {
    asm volatile("red.release.gpu.global.add.u32 [%0], 1;" :: "l"(p) : "memory");
}
__device__ __forceinline__ float sigf(float x) {
    return __fdividef(1.f, 1.f + __expf(-x));
}
__device__ __forceinline__ float tanhf2(float x) {
    return __fmaf_rn(2.f, __fdividef(1.f, 1.f + __expf(-2.f * x)), -1.f);
}

__host__ __device__ __forceinline__ int gmap(int p) { return (p & 3) * 1024 + (p >> 2); }

// ================= device scratch =================
__device__ float g_xg[(size_t)BB * SS * GG];                 // [t][b][p] xg + bias, permuted
__device__ __nv_bfloat16 g_xA[2][(size_t)BB * SS * DD];      // x hi/lo
__device__ __nv_bfloat16 g_WiB[2][DD][GG];
__device__ __nv_bfloat16 g_WhB[2][HH][GG];
__device__ __nv_bfloat16 g_hA[2][128][HH];                   // ping-pong h (hi rows 0-63, lo 64-127)
__device__ float g_cbuf[BB * HH];
__device__ float g_bias[GG];
__device__ u32 g_flags[16];

// ================= init / prep =================
__global__ void init_state(const float* __restrict__ h0, const float* __restrict__ c0,
                           const float* __restrict__ bi, const float* __restrict__ bh) {
    int i = blockIdx.x * blockDim.x + threadIdx.x;
    if (i < 16) g_flags[i] = 0;
    if (i < BB * HH) {
        int j = i % HH;
        g_cbuf[i] = c0[j];
    }
    if (i < GG) {
        int g = gmap(i);
        g_bias[i] = bi[g] + bh[g];
    }
}

__global__ void init_hA(const float* __restrict__ h0) {
    int idx = blockIdx.x * blockDim.x + threadIdx.x;
    if (idx >= BB * HH) return;
    int b = idx >> 10, j = idx & 1023;
    float v = h0[j];
    __nv_bfloat16 hi = __float2bfloat16(v);
    __nv_bfloat16 lo = __float2bfloat16(v - __bfloat162float(hi));
    g_hA[0][b][j] = hi;
    g_hA[0][b + 64][j] = lo;
}

__global__ void prep_whB(const float* __restrict__ Wh) {
    int idx = blockIdx.x * blockDim.x + threadIdx.x;
    if (idx >= GG * HH) return;
    int k = idx >> 12, p = idx & 4095;
    float v = Wh[(size_t)gmap(p) * HH + k];
    __nv_bfloat16 hi = __float2bfloat16(v);
    __nv_bfloat16 lo = __float2bfloat16(v - __bfloat162float(hi));
    g_WhB[0][k][p] = hi;
    g_WhB[1][k][p] = lo;
}

__global__ void prep_wiB(const float* __restrict__ Wi) {
    int idx = blockIdx.x * blockDim.x + threadIdx.x;
    if (idx >= GG * DD) return;
    int k = idx >> 12, p = idx & 4095;
    float v = Wi[(size_t)gmap(p) * DD + k];
    __nv_bfloat16 hi = __float2bfloat16(v);
    __nv_bfloat16 lo = __float2bfloat16(v - __bfloat162float(hi));
    g_WiB[0][k][p] = hi;
    g_WiB[1][k][p] = lo;
}

__global__ void prep_xA(const float* __restrict__ x) {
    size_t idx = (size_t)blockIdx.x * blockDim.x + threadIdx.x;
    if (idx >= (size_t)BB * SS * DD) return;
    float v = x[idx];
    __nv_bfloat16 hi = __float2bfloat16(v);
    __nv_bfloat16 lo = __float2bfloat16(v - __bfloat162float(hi));
    g_xA[0][idx] = hi;
    g_xA[1][idx] = lo;
}

// ================= input GEMM (split-2 bf16, 3 products) =================
// CTA: M=128 real rows (2 stacked subtiles of 128), N=128, K chunks of 64.
// 8 warps: st = wid>>2 (M-subtile), q = wid&3 (16 hi rows + 16 lo rows each).

#define GA0 0
#define GA1 36864
#define GB0 73728
#define GB1 108544
#define GDS 143360
#define GEMM_SMEM 210944

extern __shared__ char smx[];

__device__ __forceinline__ void g_loadA(u32 dst, int m0, int k0, int tid) {
#pragma unroll
    for (int i = 0; i < 8; i++) {
        int o = tid + i * 256;                 // 0..2047
        int stx = o >> 10;
        int r = (o >> 3) & 127;
        int seg = o & 7;
        int sp = r >> 6;
        int srow = m0 + stx * 64 + (r & 63);
        cp_async16(dst + stx * 18432 + r * 144 + seg * 16,
                   (const char*)(&g_xA[sp][0] + (size_t)srow * DD + k0) + seg * 16);
    }
}
__device__ __forceinline__ void g_loadB(u32 dst, int n0, int k0, int tid) {
#pragma unroll
    for (int i = 0; i < 8; i++) {
        int o = tid + i * 256;                 // 0..2047
        int sp = o >> 10, r = (o & 1023) >> 4, seg = o & 15;
        cp_async16(dst + sp * 17408 + r * 272 + seg * 16,
                   (const char*)(&g_WiB[sp][k0 + r][n0]) + seg * 16);
    }
}

__global__ __launch_bounds__(256, 1) void gemm_xg_mma() {
    const int tid = threadIdx.x;
    const int wid = tid >> 5, lane = tid & 31;
    const int st = wid >> 2, q = wid & 3;
    const int n0 = blockIdx.x * 128;
    const int m0 = blockIdx.y * 128;
    const u32 sb = smem_u32(smx);
    float* Ds = (float*)(smx + GDS);

    float acc[2][16][4];
#pragma unroll
    for (int a = 0; a < 2; a++)
#pragma unroll
        for (int b = 0; b < 16; b++)
#pragma unroll
            for (int c = 0; c < 4; c++) acc[a][b][c] = 0.f;

    g_loadA(sb + GA0, m0, 0, tid);
    g_loadB(sb + GB0, n0, 0, tid);
    cp_commit();

    const u32 a_ro = (q * 16 + (lane & 15)) * 144 + (lane >> 4) * 16;
    const u32 b_ro = (lane & 15) * 272 + (lane >> 4) * 16;

    for (int cc = 0; cc < 16; cc++) {
        if (cc < 15) {
            g_loadA(sb + (((cc + 1) & 1) ? GA1 : GA0), m0, (cc + 1) * 64, tid);
            g_loadB(sb + (((cc + 1) & 1) ? GB1 : GB0), n0, (cc + 1) * 64, tid);
            cp_commit();
            cp_wait<1>();
        } else {
            cp_wait<0>();
        }
        __syncthreads();

        const u32 Ab = sb + ((cc & 1) ? GA1 : GA0) + st * 18432;
        const u32 Bb = sb + ((cc & 1) ? GB1 : GB0);
#pragma unroll
        for (int kk = 0; kk < 4; kk++) {
            u32 a0, a1, a2, a3, a4, a5, a6, a7;
            u32 aaddr = Ab + a_ro + kk * 32;
            ldsm_x4(aaddr, a0, a1, a2, a3);               // hi 16 rows
            ldsm_x4(aaddr + 64 * 144, a4, a5, a6, a7);    // lo 16 rows
            u32 bbase = Bb + b_ro + kk * 16 * 272;
#pragma unroll
            for (int nt = 0; nt < 8; nt++) {              // B_hi: hi + lo rows
                u32 b0, b1, b2, b3;
                ldsm_x4t(bbase + nt * 32, b0, b1, b2, b3);
                mma16816(acc[0][nt * 2], a0, a1, a2, a3, b0, b1);
                mma16816(acc[0][nt * 2 + 1], a0, a1, a2, a3, b2, b3);
                mma16816(acc[1][nt * 2], a4, a5, a6, a7, b0, b1);
                mma16816(acc[1][nt * 2 + 1], a4, a5, a6, a7, b2, b3);
            }
#pragma unroll
            for (int nt = 0; nt < 8; nt++) {              // B_lo: hi rows only
                u32 b0, b1, b2, b3;
                ldsm_x4t(bbase + 17408 + nt * 32, b0, b1, b2, b3);
                mma16816(acc[0][nt * 2], a0, a1, a2, a3, b0, b1);
                mma16816(acc[0][nt * 2 + 1], a0, a1, a2, a3, b2, b3);
            }
        }
        __syncthreads();
    }

    const int g = lane >> 2, tq = lane & 3;
    const int rbase = st * 64 + q * 16;
    // lo partials -> Ds
#pragma unroll
    for (int nt = 0; nt < 16; nt++) {
        int c = nt * 8 + tq * 2;
        *(float2*)&Ds[(rbase + g) * 132 + c] = make_float2(acc[1][nt][0], acc[1][nt][1]);
        *(float2*)&Ds[(rbase + g + 8) * 132 + c] = make_float2(acc[1][nt][2], acc[1][nt][3]);
    }
    __syncthreads();
    // hi + lo + bias -> g_xg
#pragma unroll
    for (int nt = 0; nt < 16; nt++) {
        int c = nt * 8 + tq * 2;
        float bz0 = g_bias[n0 + c], bz1 = g_bias[n0 + c + 1];
        {
            int r = rbase + g;
            float v0 = acc[0][nt][0] + Ds[r * 132 + c] + bz0;
            float v1 = acc[0][nt][1] + Ds[r * 132 + c + 1] + bz1;
            int mg = m0 + r, bb = mg >> 9, tt = mg & 511;
            *(float2*)&g_xg[((size_t)tt * BB + bb) * GG + n0 + c] = make_float2(v0, v1);
        }
        {
            int r = rbase + g + 8;
            float v0 = acc[0][nt][2] + Ds[r * 132 + c] + bz0;
            float v1 = acc[0][nt][3] + Ds[r * 132 + c + 1] + bz1;
            int mg = m0 + r, bb = mg >> 9, tt = mg & 511;
            *(float2*)&g_xg[((size_t)tt * BB + bb) * GG + n0 + c] = make_float2(v0, v1);
        }
    }
}

// ================= persistent recurrent kernel =================
// 128 CTAs, 256 threads. CTA s owns 32 permuted cols (8 hidden units).
// Wh resident in SMEM; distributed 16-flag barrier; xg prefetched to SMEM.

#define PB 0
#define PA0 163840
#define PA1 182272
#define PXG 200704
#define PDS 208896
#define PERSIST_SMEM 227328

__device__ __forceinline__ void p_loadA(u32 dst, const __nv_bfloat16* hA, int k0, int tid) {
#pragma unroll
    for (int i = 0; i < 4; i++) {
        int o = tid + i * 256;
        int row = o >> 3, seg = o & 7;
        cp_async16_cg(dst + row * 144 + seg * 16,
                      (const char*)(hA + (size_t)row * HH + k0) + seg * 16);
    }
    cp_commit();
}

__device__ __forceinline__ void wait_step(u32 target, int tid) {
    bool ok = true;
    if (tid < 16) ok = (ld_acq(&g_flags[tid]) >= target);
    while (!__syncthreads_and(ok)) {
        __nanosleep(40);
        if (tid < 16) ok = (ld_acq(&g_flags[tid]) >= target);
    }
}

__global__ __launch_bounds__(256, 1) void lstm_persist(float* __restrict__ out) {
    const int tid = threadIdx.x;
    const int wid = tid >> 5, lane = tid & 31;
    const int wm = wid & 3, wn = wid >> 2;
    const int s = blockIdx.x;
    const int c0 = s * 32;
    const int j0 = s * 8;
    const u32 sb = smem_u32(smx);
    float* Ds = (float*)(smx + PDS);
    float* xs = (float*)(smx + PXG);

    // ---- resident Wh tiles (hi at +0, lo at +81920) ----
#pragma unroll
    for (int i = 0; i < 32; i++) {
        int o = tid + i * 256;
        int sp = o >> 12;
        int rem = o & 4095;
        int k = rem >> 2, seg = rem & 3;
        cp_async16(sb + PB + sp * 81920 + k * 80 + seg * 16,
                   (const char*)(&g_WhB[sp][k][c0]) + seg * 16);
    }
    cp_commit();
    cp_wait<0>();
    __syncthreads();

    // ---- cell state in registers: thread -> (b = tid>>2, units part*2..+1) ----
    const int eb = tid >> 2, part = tid & 3;
    float cr[2];
#pragma unroll
    for (int qq = 0; qq < 2; qq++) cr[qq] = g_cbuf[(size_t)eb * HH + j0 + part * 2 + qq];

    const u32 a_row = wm * 32 + (lane & 15);
    const u32 a_half = (lane >> 4) * 16;
    const u32 b_r = (lane & 15);
    const u32 b_cb = (wn * 16 + (lane >> 4) * 8) * 2;

    for (int t = 0; t < SS; t++) {
        const int ping = t & 1;
        const __nv_bfloat16* hA = &g_hA[ping][0][0];

        wait_step(8u * (u32)t, tid);

        float acc[2][2][4];
#pragma unroll
        for (int a = 0; a < 2; a++)
#pragma unroll
            for (int b = 0; b < 2; b++)
#pragma unroll
                for (int qq = 0; qq < 4; qq++) acc[a][b][qq] = 0.f;

        // xg prefetch (with first A chunk's commit group)
#pragma unroll
        for (int i = 0; i < 2; i++) {
            int o = tid + i * 256;
            int b = o >> 3, seg = o & 7;
            cp_async16(sb + PXG + b * 128 + seg * 16,
                       (const char*)(g_xg + ((size_t)t * BB + b) * GG + c0) + seg * 16);
        }
        p_loadA(sb + PA0, hA, 0, tid);

        for (int cc = 0; cc < 16; cc++) {
            if (cc < 15) {
                p_loadA(sb + (((cc + 1) & 1) ? PA1 : PA0), hA, (cc + 1) * 64, tid);
                cp_wait<1>();
            } else {
                cp_wait<0>();
            }
            __syncthreads();

            const u32 Ab = sb + ((cc & 1) ? PA1 : PA0);
#pragma unroll
            for (int kk = 0; kk < 4; kk++) {
                u32 a0, a1, a2, a3, a4, a5, a6, a7;
                u32 aaddr = Ab + a_row * 144 + kk * 32 + a_half;
                ldsm_x4(aaddr, a0, a1, a2, a3);
                ldsm_x4(aaddr + 16 * 144, a4, a5, a6, a7);
                u32 b0, b1, b2, b3, b4, b5, b6, b7;
                u32 baddr = sb + PB + (cc * 64 + kk * 16 + b_r) * 80 + b_cb;
                ldsm_x4t(baddr, b0, b1, b2, b3);
                ldsm_x4t(baddr + 81920, b4, b5, b6, b7);
                mma16816(acc[0][0], a0, a1, a2, a3, b0, b1);
                mma16816(acc[0][1], a0, a1, a2, a3, b2, b3);
                mma16816(acc[1][0], a4, a5, a6, a7, b0, b1);
                mma16816(acc[1][1], a4, a5, a6, a7, b2, b3);
                mma16816(acc[0][0], a0, a1, a2, a3, b4, b5);   // hi rows x W_lo
                mma16816(acc[0][1], a0, a1, a2, a3, b6, b7);
            }
            __syncthreads();
        }

        // dump accumulators to Ds[128][36]
        {
            const int g = lane >> 2, tq = lane & 3;
#pragma unroll
            for (int mt = 0; mt < 2; mt++)
#pragma unroll
                for (int nt = 0; nt < 2; nt++) {
                    int r = wm * 32 + mt * 16 + g;
                    int c = wn * 16 + nt * 8 + tq * 2;
                    *(float2*)&Ds[r * 36 + c] = make_float2(acc[mt][nt][0], acc[mt][nt][1]);
                    *(float2*)&Ds[(r + 8) * 36 + c] = make_float2(acc[mt][nt][2], acc[mt][nt][3]);
                }
        }
        __syncthreads();

        // epilogue: 256 threads x 2 hidden units
        {
            const float* dh = Ds + eb * 36;
            const float* dl = Ds + (eb + 64) * 36;
            const float* xr = xs + eb * 32;
            float hv[2];
            u32 hiw = 0, low = 0;
#pragma unroll
            for (int qq = 0; qq < 2; qq++) {
                int u = part * 2 + qq;
                float gi = dh[u * 4 + 0] + dl[u * 4 + 0] + xr[u * 4 + 0];
                float gf = dh[u * 4 + 1] + dl[u * 4 + 1] + xr[u * 4 + 1];
                float gg = dh[u * 4 + 2] + dl[u * 4 + 2] + xr[u * 4 + 2];
                float go = dh[u * 4 + 3] + dl[u * 4 + 3] + xr[u * 4 + 3];
                float c = sigf(gf) * cr[qq] + sigf(gi) * tanhf2(gg);
                cr[qq] = c;
                float h = sigf(go) * tanhf2(c);
                hv[qq] = h;
                __nv_bfloat16 hi = __float2bfloat16(h);
                __nv_bfloat16 lo = __float2bfloat16(h - __bfloat162float(hi));
                hiw |= (u32)*(unsigned short*)&hi << (qq * 16);
                low |= (u32)*(unsigned short*)&lo << (qq * 16);
            }
            *(float2*)&out[((size_t)eb * SS + t) * HH + j0 + part * 2] = make_float2(hv[0], hv[1]);
            *(u32*)&g_hA[ping ^ 1][eb][j0 + part * 2] = hiw;
            *(u32*)&g_hA[ping ^ 1][eb + 64][j0 + part * 2] = low;
        }
        __syncthreads();
        if (tid == 0) red_release(&g_flags[s >> 3]);
    }

#pragma unroll
    for (int qq = 0; qq < 2; qq++)
        g_cbuf[(size_t)eb * HH + j0 + part * 2 + qq] = cr[qq];
}

// ================= tail =================
__global__ void write_tail(float* __restrict__ out, long long hsz, int want_c) {
    int i = blockIdx.x * blockDim.x + threadIdx.x;
    if (i < BB * HH) {
        int b = i / HH, j = i % HH;
        out[hsz + i] = out[((size_t)b * SS + (SS - 1)) * HH + j];
        if (want_c) out[hsz + (long long)BB * HH + i] = g_cbuf[i];
    }
}

// ================= launch =================
extern "C" void kernel_launch(void* const* d_in, const int* in_sizes, int n_in,
                              void* d_out, int out_size) {
    const float* x  = (const float*)d_in[0];
    const float* h0 = (const float*)d_in[1];
    const float* c0 = (const float*)d_in[2];
    const float* Wi = (const float*)d_in[3];
    const float* bi = (const float*)d_in[4];
    const float* Wh = (const float*)d_in[5];
    const float* bh = (const float*)d_in[6];
    float* out = (float*)d_out;

    cudaFuncSetAttribute(gemm_xg_mma, cudaFuncAttributeMaxDynamicSharedMemorySize, GEMM_SMEM);
    cudaFuncSetAttribute(lstm_persist, cudaFuncAttributeMaxDynamicSharedMemorySize, PERSIST_SMEM);

    init_state<<<(BB * HH + 255) / 256, 256>>>(h0, c0, bi, bh);
    init_hA<<<(BB * HH + 255) / 256, 256>>>(h0);
    prep_whB<<<(GG * HH) / 256, 256>>>(Wh);
    prep_wiB<<<(GG * DD) / 256, 256>>>(Wi);
    prep_xA<<<(int)(((size_t)BB * SS * DD) / 256), 256>>>(x);

    dim3 gg(GG / 128, (BB * SS) / 128);
    gemm_xg_mma<<<gg, 256, GEMM_SMEM>>>();

    lstm_persist<<<128, 256, PERSIST_SMEM>>>(out);

    long long hsz = (long long)BB * SS * HH;
    int want_h = ((long long)out_size >= hsz + (long long)BB * HH) ? 1 : 0;
    int want_c = ((long long)out_size >= hsz + 2LL * BB * HH) ? 1 : 0;
    if (want_h) {
        write_tail<<<(BB * HH + 255) / 256, 256>>>(out, hsz, want_c);
    }
}

// round 7
// speedup vs baseline: 4.1777x; 1.0087x over previous
#include <cuda_runtime.h>
#include <cuda_bf16.h>
#include <math.h>

#define BB 64
#define SS 512
#define DD 1024
#define HH 1024
#define GG 4096

typedef unsigned int u32;

// ================= helpers =================
__device__ __forceinline__ void cp_async16(unsigned s, const void* g) {
    asm volatile("cp.async.ca.shared.global [%0], [%1], 16;" :: "r"(s), "l"(g));
}
__device__ __forceinline__ void cp_async16_cg(unsigned s, const void* g) {
    asm volatile("cp.async.cg.shared.global [%0], [%1], 16;" :: "r"(s), "l"(g));
}
__device__ __forceinline__ void cp_commit() { asm volatile("cp.async.commit_group;"); }
template<int N> __device__ __forceinline__ void cp_wait() {
    asm volatile("cp.async.wait_group %0;" :: "n"(N));
}
__device__ __forceinline__ u32 smem_u32(const void* p) {
    u32 a;
    asm("{ .reg .u64 t; cvta.to.shared.u64 t, %1; cvt.u32.u64 %0, t; }" : "=r"(a) : "l"(p));
    return a;
}
__device__ __forceinline__ void ldsm_x4(u32 addr, u32& r0, u32& r1, u32& r2, u32& r3) {
    asm volatile("ldmatrix.sync.aligned.m8n8.x4.shared.b16 {%0,%1,%2,%3}, [%4];"
                 : "=r"(r0), "=r"(r1), "=r"(r2), "=r"(r3) : "r"(addr));
}
__device__ __forceinline__ void ldsm_x4t(u32 addr, u32& r0, u32& r1, u32& r2, u32& r3) {
    asm volatile("ldmatrix.sync.aligned.m8n8.x4.trans.shared.b16 {%0,%1,%2,%3}, [%4];"
                 : "=r"(r0), "=r"(r1), "=r"(r2), "=r"(r3) : "r"(addr));
}
__device__ __forceinline__ void mma16816(float* c, u32 a0, u32 a1, u32 a2, u32 a3, u32 b0, u32 b1) {
    asm volatile("mma.sync.aligned.m16n8k16.row.col.f32.bf16.bf16.f32 "
                 "{%0,%1,%2,%3},{%4,%5,%6,%7},{%8,%9},{%0,%1,%2,%3};"
                 : "+f"(c[0]), "+f"(c[1]), "+f"(c[2]), "+f"(c[3])
                 : "r"(a0), "r"(a1), "r"(a2), "r"(a3), "r"(b0), "r"(b1));
}
__device__ __forceinline__ u32 ld_acq(const u32* p) {
    u32 v;
    asm volatile("ld.acquire.gpu.global.u32 %0, [%1];" : "=r"(v) : "l"(p) : "memory");
    return v;
}
__device__ __forceinline__ void red_release(u32* p) {
    asm volatile("red.release.gpu.global.add.u32 [%0], 1;" :: "l"(p) : "memory");
}
// precise gates: sigma(x) = 0.5 + 0.5*tanh(x/2), tanh = libm tanhf
__device__ __forceinline__ float sigf(float x) {
    return __fmaf_rn(0.5f, tanhf(0.5f * x), 0.5f);
}

__host__ __device__ __forceinline__ int gmap(int p) { return (p & 3) * 1024 + (p >> 2); }

// ================= device scratch =================
__device__ float g_xg[(size_t)BB * SS * GG];                 // [t][b][p] xg + bias, permuted
__device__ __nv_bfloat16 g_xA[2][(size_t)BB * SS * DD];      // x hi/lo
__device__ __nv_bfloat16 g_WiB[2][DD][GG];
__device__ __nv_bfloat16 g_WhB[2][HH][GG];
__device__ __nv_bfloat16 g_hA[2][128][HH];                   // ping-pong h (hi rows 0-63, lo 64-127)
__device__ float g_cbuf[BB * HH];
__device__ float g_bias[GG];
__device__ u32 g_flags[16];

// ================= init / prep =================
__global__ void init_state(const float* __restrict__ h0, const float* __restrict__ c0,
                           const float* __restrict__ bi, const float* __restrict__ bh) {
    int i = blockIdx.x * blockDim.x + threadIdx.x;
    if (i < 16) g_flags[i] = 0;
    if (i < BB * HH) {
        int j = i % HH;
        g_cbuf[i] = c0[j];
    }
    if (i < GG) {
        int g = gmap(i);
        g_bias[i] = bi[g] + bh[g];
    }
}

__global__ void init_hA(const float* __restrict__ h0) {
    int idx = blockIdx.x * blockDim.x + threadIdx.x;
    if (idx >= BB * HH) return;
    int b = idx >> 10, j = idx & 1023;
    float v = h0[j];
    __nv_bfloat16 hi = __float2bfloat16(v);
    __nv_bfloat16 lo = __float2bfloat16(v - __bfloat162float(hi));
    g_hA[0][b][j] = hi;
    g_hA[0][b + 64][j] = lo;
}

__global__ void prep_whB(const float* __restrict__ Wh) {
    int idx = blockIdx.x * blockDim.x + threadIdx.x;
    if (idx >= GG * HH) return;
    int k = idx >> 12, p = idx & 4095;
    float v = Wh[(size_t)gmap(p) * HH + k];
    __nv_bfloat16 hi = __float2bfloat16(v);
    __nv_bfloat16 lo = __float2bfloat16(v - __bfloat162float(hi));
    g_WhB[0][k][p] = hi;
    g_WhB[1][k][p] = lo;
}

__global__ void prep_wiB(const float* __restrict__ Wi) {
    int idx = blockIdx.x * blockDim.x + threadIdx.x;
    if (idx >= GG * DD) return;
    int k = idx >> 12, p = idx & 4095;
    float v = Wi[(size_t)gmap(p) * DD + k];
    __nv_bfloat16 hi = __float2bfloat16(v);
    __nv_bfloat16 lo = __float2bfloat16(v - __bfloat162float(hi));
    g_WiB[0][k][p] = hi;
    g_WiB[1][k][p] = lo;
}

__global__ void prep_xA(const float* __restrict__ x) {
    size_t i4 = (size_t)blockIdx.x * blockDim.x + threadIdx.x;
    if (i4 >= (size_t)BB * SS * DD / 4) return;
    float4 v = *(const float4*)(x + i4 * 4);
    __nv_bfloat16 h0 = __float2bfloat16(v.x), h1 = __float2bfloat16(v.y);
    __nv_bfloat16 h2 = __float2bfloat16(v.z), h3 = __float2bfloat16(v.w);
    __nv_bfloat16 l0 = __float2bfloat16(v.x - __bfloat162float(h0));
    __nv_bfloat16 l1 = __float2bfloat16(v.y - __bfloat162float(h1));
    __nv_bfloat16 l2 = __float2bfloat16(v.z - __bfloat162float(h2));
    __nv_bfloat16 l3 = __float2bfloat16(v.w - __bfloat162float(h3));
    __nv_bfloat162 hp0 = {h0, h1}, hp1 = {h2, h3}, lp0 = {l0, l1}, lp1 = {l2, l3};
    uint2 hw = {*(u32*)&hp0, *(u32*)&hp1};
    uint2 lw = {*(u32*)&lp0, *(u32*)&lp1};
    *(uint2*)(&g_xA[0][0] + i4 * 4) = hw;
    *(uint2*)(&g_xA[1][0] + i4 * 4) = lw;
}

// ================= input GEMM (split-2 bf16, 3 products) =================

#define GA0 0
#define GA1 36864
#define GB0 73728
#define GB1 108544
#define GDS 143360
#define GEMM_SMEM 210944

extern __shared__ char smx[];

__device__ __forceinline__ void g_loadA(u32 dst, int m0, int k0, int tid) {
#pragma unroll
    for (int i = 0; i < 8; i++) {
        int o = tid + i * 256;
        int stx = o >> 10;
        int r = (o >> 3) & 127;
        int seg = o & 7;
        int sp = r >> 6;
        int srow = m0 + stx * 64 + (r & 63);
        cp_async16(dst + stx * 18432 + r * 144 + seg * 16,
                   (const char*)(&g_xA[sp][0] + (size_t)srow * DD + k0) + seg * 16);
    }
}
__device__ __forceinline__ void g_loadB(u32 dst, int n0, int k0, int tid) {
#pragma unroll
    for (int i = 0; i < 8; i++) {
        int o = tid + i * 256;
        int sp = o >> 10, r = (o & 1023) >> 4, seg = o & 15;
        cp_async16(dst + sp * 17408 + r * 272 + seg * 16,
                   (const char*)(&g_WiB[sp][k0 + r][n0]) + seg * 16);
    }
}

__global__ __launch_bounds__(256, 1) void gemm_xg_mma() {
    const int tid = threadIdx.x;
    const int wid = tid >> 5, lane = tid & 31;
    const int st = wid >> 2, q = wid & 3;
    const int n0 = blockIdx.x * 128;
    const int m0 = blockIdx.y * 128;
    const u32 sb = smem_u32(smx);
    float* Ds = (float*)(smx + GDS);

    float acc[2][16][4];
#pragma unroll
    for (int a = 0; a < 2; a++)
#pragma unroll
        for (int b = 0; b < 16; b++)
#pragma unroll
            for (int c = 0; c < 4; c++) acc[a][b][c] = 0.f;

    g_loadA(sb + GA0, m0, 0, tid);
    g_loadB(sb + GB0, n0, 0, tid);
    cp_commit();

    const u32 a_ro = (q * 16 + (lane & 15)) * 144 + (lane >> 4) * 16;
    const u32 b_ro = (lane & 15) * 272 + (lane >> 4) * 16;

    for (int cc = 0; cc < 16; cc++) {
        if (cc < 15) {
            g_loadA(sb + (((cc + 1) & 1) ? GA1 : GA0), m0, (cc + 1) * 64, tid);
            g_loadB(sb + (((cc + 1) & 1) ? GB1 : GB0), n0, (cc + 1) * 64, tid);
            cp_commit();
            cp_wait<1>();
        } else {
            cp_wait<0>();
        }
        __syncthreads();

        const u32 Ab = sb + ((cc & 1) ? GA1 : GA0) + st * 18432;
        const u32 Bb = sb + ((cc & 1) ? GB1 : GB0);
#pragma unroll
        for (int kk = 0; kk < 4; kk++) {
            u32 a0, a1, a2, a3, a4, a5, a6, a7;
            u32 aaddr = Ab + a_ro + kk * 32;
            ldsm_x4(aaddr, a0, a1, a2, a3);
            ldsm_x4(aaddr + 64 * 144, a4, a5, a6, a7);
            u32 bbase = Bb + b_ro + kk * 16 * 272;
#pragma unroll
            for (int nt = 0; nt < 8; nt++) {
                u32 b0, b1, b2, b3;
                ldsm_x4t(bbase + nt * 32, b0, b1, b2, b3);
                mma16816(acc[0][nt * 2], a0, a1, a2, a3, b0, b1);
                mma16816(acc[0][nt * 2 + 1], a0, a1, a2, a3, b2, b3);
                mma16816(acc[1][nt * 2], a4, a5, a6, a7, b0, b1);
                mma16816(acc[1][nt * 2 + 1], a4, a5, a6, a7, b2, b3);
            }
#pragma unroll
            for (int nt = 0; nt < 8; nt++) {
                u32 b0, b1, b2, b3;
                ldsm_x4t(bbase + 17408 + nt * 32, b0, b1, b2, b3);
                mma16816(acc[0][nt * 2], a0, a1, a2, a3, b0, b1);
                mma16816(acc[0][nt * 2 + 1], a0, a1, a2, a3, b2, b3);
            }
        }
        __syncthreads();
    }

    const int g = lane >> 2, tq = lane & 3;
    const int rbase = st * 64 + q * 16;
#pragma unroll
    for (int nt = 0; nt < 16; nt++) {
        int c = nt * 8 + tq * 2;
        *(float2*)&Ds[(rbase + g) * 132 + c] = make_float2(acc[1][nt][0], acc[1][nt][1]);
        *(float2*)&Ds[(rbase + g + 8) * 132 + c] = make_float2(acc[1][nt][2], acc[1][nt][3]);
    }
    __syncthreads();
#pragma unroll
    for (int nt = 0; nt < 16; nt++) {
        int c = nt * 8 + tq * 2;
        float bz0 = g_bias[n0 + c], bz1 = g_bias[n0 + c + 1];
        {
            int r = rbase + g;
            float v0 = acc[0][nt][0] + Ds[r * 132 + c] + bz0;
            float v1 = acc[0][nt][1] + Ds[r * 132 + c + 1] + bz1;
            int mg = m0 + r, bb = mg >> 9, tt = mg & 511;
            *(float2*)&g_xg[((size_t)tt * BB + bb) * GG + n0 + c] = make_float2(v0, v1);
        }
        {
            int r = rbase + g + 8;
            float v0 = acc[0][nt][2] + Ds[r * 132 + c] + bz0;
            float v1 = acc[0][nt][3] + Ds[r * 132 + c + 1] + bz1;
            int mg = m0 + r, bb = mg >> 9, tt = mg & 511;
            *(float2*)&g_xg[((size_t)tt * BB + bb) * GG + n0 + c] = make_float2(v0, v1);
        }
    }
}

// ================= persistent recurrent kernel =================

#define PB 0
#define PA0 163840
#define PA1 182272
#define PXG 200704
#define PDS 208896
#define PERSIST_SMEM 227328

__device__ __forceinline__ void p_loadA(u32 dst, const __nv_bfloat16* hA, int k0, int tid) {
#pragma unroll
    for (int i = 0; i < 4; i++) {
        int o = tid + i * 256;
        int row = o >> 3, seg = o & 7;
        cp_async16_cg(dst + row * 144 + seg * 16,
                      (const char*)(hA + (size_t)row * HH + k0) + seg * 16);
    }
    cp_commit();
}

__device__ __forceinline__ void wait_step(u32 target, int tid) {
    bool ok = true;
    if (tid < 16) ok = (ld_acq(&g_flags[tid]) >= target);
    while (!__syncthreads_and(ok)) {
        __nanosleep(40);
        if (tid < 16) ok = (ld_acq(&g_flags[tid]) >= target);
    }
}

__global__ __launch_bounds__(256, 1) void lstm_persist(float* __restrict__ out) {
    const int tid = threadIdx.x;
    const int wid = tid >> 5, lane = tid & 31;
    const int wm = wid & 3, wn = wid >> 2;
    const int s = blockIdx.x;
    const int c0 = s * 32;
    const int j0 = s * 8;
    const u32 sb = smem_u32(smx);
    float* Ds = (float*)(smx + PDS);
    float* xs = (float*)(smx + PXG);

    // ---- resident Wh tiles (hi at +0, lo at +81920) ----
#pragma unroll
    for (int i = 0; i < 32; i++) {
        int o = tid + i * 256;
        int sp = o >> 12;
        int rem = o & 4095;
        int k = rem >> 2, seg = rem & 3;
        cp_async16(sb + PB + sp * 81920 + k * 80 + seg * 16,
                   (const char*)(&g_WhB[sp][k][c0]) + seg * 16);
    }
    cp_commit();
    cp_wait<0>();
    __syncthreads();

    const int eb = tid >> 2, part = tid & 3;
    float cr[2];
#pragma unroll
    for (int qq = 0; qq < 2; qq++) cr[qq] = g_cbuf[(size_t)eb * HH + j0 + part * 2 + qq];

    const u32 a_row = wm * 32 + (lane & 15);
    const u32 a_half = (lane >> 4) * 16;
    const u32 b_r = (lane & 15);
    const u32 b_cb = (wn * 16 + (lane >> 4) * 8) * 2;

    for (int t = 0; t < SS; t++) {
        const int ping = t & 1;
        const __nv_bfloat16* hA = &g_hA[ping][0][0];

        wait_step(8u * (u32)t, tid);

        float acc[2][2][4];
#pragma unroll
        for (int a = 0; a < 2; a++)
#pragma unroll
            for (int b = 0; b < 2; b++)
#pragma unroll
                for (int qq = 0; qq < 4; qq++) acc[a][b][qq] = 0.f;

        // xg prefetch shares chunk0's commit group
#pragma unroll
        for (int i = 0; i < 2; i++) {
            int o = tid + i * 256;
            int b = o >> 3, seg = o & 7;
            cp_async16(sb + PXG + b * 128 + seg * 16,
                       (const char*)(g_xg + ((size_t)t * BB + b) * GG + c0) + seg * 16);
        }
        p_loadA(sb + PA0, hA, 0, tid);

        for (int cc = 0; cc < 16; cc++) {
            if (cc < 15) {
                p_loadA(sb + (((cc + 1) & 1) ? PA1 : PA0), hA, (cc + 1) * 64, tid);
                cp_wait<1>();
            } else {
                cp_wait<0>();
            }
            __syncthreads();

            const u32 Ab = sb + ((cc & 1) ? PA1 : PA0);
#pragma unroll
            for (int kk = 0; kk < 4; kk++) {
                u32 a0, a1, a2, a3, a4, a5, a6, a7;
                u32 aaddr = Ab + a_row * 144 + kk * 32 + a_half;
                ldsm_x4(aaddr, a0, a1, a2, a3);
                ldsm_x4(aaddr + 16 * 144, a4, a5, a6, a7);
                u32 b0, b1, b2, b3, b4, b5, b6, b7;
                u32 baddr = sb + PB + (cc * 64 + kk * 16 + b_r) * 80 + b_cb;
                ldsm_x4t(baddr, b0, b1, b2, b3);
                ldsm_x4t(baddr + 81920, b4, b5, b6, b7);
                mma16816(acc[0][0], a0, a1, a2, a3, b0, b1);
                mma16816(acc[0][1], a0, a1, a2, a3, b2, b3);
                mma16816(acc[1][0], a4, a5, a6, a7, b0, b1);
                mma16816(acc[1][1], a4, a5, a6, a7, b2, b3);
                mma16816(acc[0][0], a0, a1, a2, a3, b4, b5);   // hi rows x W_lo
                mma16816(acc[0][1], a0, a1, a2, a3, b6, b7);
            }
            __syncthreads();
        }

        // dump accumulators to Ds[128][36]
        {
            const int g = lane >> 2, tq = lane & 3;
#pragma unroll
            for (int mt = 0; mt < 2; mt++)
#pragma unroll
                for (int nt = 0; nt < 2; nt++) {
                    int r = wm * 32 + mt * 16 + g;
                    int c = wn * 16 + nt * 8 + tq * 2;
                    *(float2*)&Ds[r * 36 + c] = make_float2(acc[mt][nt][0], acc[mt][nt][1]);
                    *(float2*)&Ds[(r + 8) * 36 + c] = make_float2(acc[mt][nt][2], acc[mt][nt][3]);
                }
        }
        __syncthreads();

        // epilogue: 256 threads x 2 hidden units; precise gates
        float hv[2];
        {
            const float* dh = Ds + eb * 36;
            const float* dl = Ds + (eb + 64) * 36;
            const float* xr = xs + eb * 32;
            u32 hiw = 0, low = 0;
#pragma unroll
            for (int qq = 0; qq < 2; qq++) {
                int u = part * 2 + qq;
                float gi = dh[u * 4 + 0] + dl[u * 4 + 0] + xr[u * 4 + 0];
                float gf = dh[u * 4 + 1] + dl[u * 4 + 1] + xr[u * 4 + 1];
                float gg = dh[u * 4 + 2] + dl[u * 4 + 2] + xr[u * 4 + 2];
                float go = dh[u * 4 + 3] + dl[u * 4 + 3] + xr[u * 4 + 3];
                float c = sigf(gf) * cr[qq] + sigf(gi) * tanhf(gg);
                cr[qq] = c;
                float h = sigf(go) * tanhf(c);
                hv[qq] = h;
                __nv_bfloat16 hi = __float2bfloat16(h);
                __nv_bfloat16 lo = __float2bfloat16(h - __bfloat162float(hi));
                hiw |= (u32)*(unsigned short*)&hi << (qq * 16);
                low |= (u32)*(unsigned short*)&lo << (qq * 16);
            }
            // next-step h tiles FIRST (they gate the other CTAs)
            *(u32*)&g_hA[ping ^ 1][eb][j0 + part * 2] = hiw;
            *(u32*)&g_hA[ping ^ 1][eb + 64][j0 + part * 2] = low;
        }
        __syncthreads();
        if (tid == 0) red_release(&g_flags[s >> 3]);
        // out store off the critical path
        *(float2*)&out[((size_t)eb * SS + t) * HH + j0 + part * 2] = make_float2(hv[0], hv[1]);
    }

#pragma unroll
    for (int qq = 0; qq < 2; qq++)
        g_cbuf[(size_t)eb * HH + j0 + part * 2 + qq] = cr[qq];
}

// ================= tail =================
__global__ void write_tail(float* __restrict__ out, long long hsz, int want_c) {
    int i = blockIdx.x * blockDim.x + threadIdx.x;
    if (i < BB * HH) {
        int b = i / HH, j = i % HH;
        out[hsz + i] = out[((size_t)b * SS + (SS - 1)) * HH + j];
        if (want_c) out[hsz + (long long)BB * HH + i] = g_cbuf[i];
    }
}

// ================= launch =================
extern "C" void kernel_launch(void* const* d_in, const int* in_sizes, int n_in,
                              void* d_out, int out_size) {
    const float* x  = (const float*)d_in[0];
    const float* h0 = (const float*)d_in[1];
    const float* c0 = (const float*)d_in[2];
    const float* Wi = (const float*)d_in[3];
    const float* bi = (const float*)d_in[4];
    const float* Wh = (const float*)d_in[5];
    const float* bh = (const float*)d_in[6];
    float* out = (float*)d_out;

    cudaFuncSetAttribute(gemm_xg_mma, cudaFuncAttributeMaxDynamicSharedMemorySize, GEMM_SMEM);
    cudaFuncSetAttribute(lstm_persist, cudaFuncAttributeMaxDynamicSharedMemorySize, PERSIST_SMEM);

    init_state<<<(BB * HH + 255) / 256, 256>>>(h0, c0, bi, bh);
    init_hA<<<(BB * HH + 255) / 256, 256>>>(h0);
    prep_whB<<<(GG * HH) / 256, 256>>>(Wh);
    prep_wiB<<<(GG * DD) / 256, 256>>>(Wi);
    prep_xA<<<(int)(((size_t)BB * SS * DD / 4) / 256), 256>>>(x);

    dim3 gg(GG / 128, (BB * SS) / 128);
    gemm_xg_mma<<<gg, 256, GEMM_SMEM>>>();

    lstm_persist<<<128, 256, PERSIST_SMEM>>>(out);

    long long hsz = (long long)BB * SS * HH;
    int want_h = ((long long)out_size >= hsz + (long long)BB * HH) ? 1 : 0;
    int want_c = ((long long)out_size >= hsz + 2LL * BB * HH) ? 1 : 0;
    if (want_h) {
        write_tail<<<(BB * HH + 255) / 256, 256>>>(out, hsz, want_c);
    }
}